// round 1
// baseline (speedup 1.0000x reference)
#include <cuda_runtime.h>

// ===== Problem-sized static scratch (allocation-free rule: __device__ globals) =====
#define N_MAX 100352
#define E_MAX 1700032

__device__ int   g_cnt[N_MAX];
__device__ int   g_fill[N_MAX];
__device__ int   g_off[N_MAX + 1];
__device__ int   g_bsum[1024];
__device__ float g_dinv[N_MAX];
__device__ int   g_src[E_MAX];
__device__ float g_w[E_MAX];

__device__ float g_X [(size_t)N_MAX * 128];  // [latent@W1 | cond@W2]
__device__ float g_H [(size_t)N_MAX * 128];  // aggregated h (128)
__device__ float g_T [(size_t)N_MAX * 64];   // h@W3
__device__ float g_H2[(size_t)N_MAX * 64];   // aggregated (64)

// ============================ graph construction ============================

__global__ void k_zero(int n) {
    int i = blockIdx.x * blockDim.x + threadIdx.x;
    if (i < n) { g_cnt[i] = 0; g_fill[i] = 0; }
}

__global__ void k_hist(const int* __restrict__ col, int E) {
    int e = blockIdx.x * blockDim.x + threadIdx.x;
    if (e < E) atomicAdd(&g_cnt[col[e]], 1);
}

// block-local exclusive scan (Hillis-Steele inclusive, then subtract v)
__global__ void k_scan_local(int n) {
    __shared__ int s[1024];
    int tid = threadIdx.x;
    int i = blockIdx.x * 1024 + tid;
    int v = (i < n) ? g_cnt[i] : 0;
    s[tid] = v;
    __syncthreads();
    for (int d = 1; d < 1024; d <<= 1) {
        int t = (tid >= d) ? s[tid - d] : 0;
        __syncthreads();
        s[tid] += t;
        __syncthreads();
    }
    if (i < n) g_off[i] = s[tid] - v;
    if (tid == 1023) g_bsum[blockIdx.x] = s[1023];
}

__global__ void k_scan_bsum(int nb) {
    __shared__ int s[1024];
    int tid = threadIdx.x;
    int v = (tid < nb) ? g_bsum[tid] : 0;
    s[tid] = v;
    __syncthreads();
    for (int d = 1; d < 1024; d <<= 1) {
        int t = (tid >= d) ? s[tid - d] : 0;
        __syncthreads();
        s[tid] += t;
        __syncthreads();
    }
    if (tid < nb) g_bsum[tid] = s[tid] - v;  // exclusive
}

__global__ void k_scan_add(int n, int E) {
    int i = blockIdx.x * blockDim.x + threadIdx.x;
    if (i < n) {
        g_off[i] += g_bsum[i >> 10];
        g_dinv[i] = rsqrtf((float)(g_cnt[i] + 1));  // +1 self loop; always > 0
    }
    if (i == n) g_off[n] = E;
}

__global__ void k_fill(const int* __restrict__ row, const int* __restrict__ col, int E) {
    int e = blockIdx.x * blockDim.x + threadIdx.x;
    if (e < E) {
        int r = row[e], c = col[e];
        int pos = g_off[c] + atomicAdd(&g_fill[c], 1);
        g_src[pos] = r;
        g_w[pos]   = g_dinv[r];
    }
}

// ============================ dense GEMM (small) ============================
// acc[64] = a[0..FIN) @ sW[FIN,64]
template <int FIN>
__device__ __forceinline__ void dot64(const float* __restrict__ a,
                                      const float* __restrict__ sW,
                                      float* acc) {
#pragma unroll
    for (int j = 0; j < 64; j++) acc[j] = 0.f;
#pragma unroll 4
    for (int k = 0; k < FIN; k += 4) {
        float4 av = *reinterpret_cast<const float4*>(a + k);
#pragma unroll
        for (int j = 0; j < 64; j += 4) {
            float4 w0 = *reinterpret_cast<const float4*>(sW + (k + 0) * 64 + j);
            float4 w1 = *reinterpret_cast<const float4*>(sW + (k + 1) * 64 + j);
            float4 w2 = *reinterpret_cast<const float4*>(sW + (k + 2) * 64 + j);
            float4 w3 = *reinterpret_cast<const float4*>(sW + (k + 3) * 64 + j);
            acc[j + 0] += av.x * w0.x + av.y * w1.x + av.z * w2.x + av.w * w3.x;
            acc[j + 1] += av.x * w0.y + av.y * w1.y + av.z * w2.y + av.w * w3.y;
            acc[j + 2] += av.x * w0.z + av.y * w1.z + av.z * w2.z + av.w * w3.z;
            acc[j + 3] += av.x * w0.w + av.y * w1.w + av.z * w2.w + av.w * w3.w;
        }
    }
}

// X[:,0:64) = latent@W1 ; X[:,64:128) = cond@W2   (biases added post-aggregation)
__global__ void k_gemm_fused(const float* __restrict__ latent,
                             const float* __restrict__ cond,
                             const float* __restrict__ W1,
                             const float* __restrict__ W2,
                             float* __restrict__ X, int n) {
    __shared__ float sW1[64 * 64];
    __shared__ float sW2[32 * 64];
    for (int i = threadIdx.x; i < 64 * 64; i += blockDim.x) sW1[i] = W1[i];
    for (int i = threadIdx.x; i < 32 * 64; i += blockDim.x) sW2[i] = W2[i];
    __syncthreads();
    int node = blockIdx.x * blockDim.x + threadIdx.x;
    if (node >= n) return;
    float acc[64];
    float* xp = X + (size_t)node * 128;
    dot64<64>(latent + (size_t)node * 64, sW1, acc);
#pragma unroll
    for (int j = 0; j < 64; j += 4)
        *reinterpret_cast<float4*>(xp + j) = make_float4(acc[j], acc[j + 1], acc[j + 2], acc[j + 3]);
    dot64<32>(cond + (size_t)node * 32, sW2, acc);
#pragma unroll
    for (int j = 0; j < 64; j += 4)
        *reinterpret_cast<float4*>(xp + 64 + j) = make_float4(acc[j], acc[j + 1], acc[j + 2], acc[j + 3]);
}

template <int FIN>
__global__ void k_gemm64(const float* __restrict__ A,
                         const float* __restrict__ W,
                         float* __restrict__ Y, int n) {
    __shared__ float sW[FIN * 64];
    for (int i = threadIdx.x; i < FIN * 64; i += blockDim.x) sW[i] = W[i];
    __syncthreads();
    int node = blockIdx.x * blockDim.x + threadIdx.x;
    if (node >= n) return;
    float acc[64];
    dot64<FIN>(A + (size_t)node * FIN, sW, acc);
    float* yp = Y + (size_t)node * 64;
#pragma unroll
    for (int j = 0; j < 64; j += 4)
        *reinterpret_cast<float4*>(yp + j) = make_float4(acc[j], acc[j + 1], acc[j + 2], acc[j + 3]);
}

// ============================ CSR aggregation ============================
// Y[c] = dinv[c] * ( sum_{e: col=c} dinv[src_e] * X[src_e]  +  dinv[c]*X[c] ) + bias
// One warp per node; lane handles F/32 contiguous features (vectorized).

__device__ __forceinline__ void fmaV4(float* acc, const float* p, float w) {
    float4 x = *reinterpret_cast<const float4*>(p);
    acc[0] += w * x.x; acc[1] += w * x.y; acc[2] += w * x.z; acc[3] += w * x.w;
}
__device__ __forceinline__ void fmaV2(float* acc, const float* p, float w) {
    float2 x = *reinterpret_cast<const float2*>(p);
    acc[0] += w * x.x; acc[1] += w * x.y;
}

template <int F>
__global__ void k_agg(const float* __restrict__ X, float* __restrict__ Y,
                      const float* __restrict__ blo, const float* __restrict__ bhi,
                      int n) {
    int wid  = (blockIdx.x * blockDim.x + threadIdx.x) >> 5;
    int lane = threadIdx.x & 31;
    if (wid >= n) return;
    constexpr int V = F / 32;  // 4 or 2
    const int f0 = lane * V;

    int e = g_off[wid];
    const int end = g_off[wid + 1];
    float acc[V];
#pragma unroll
    for (int v = 0; v < V; v++) acc[v] = 0.f;

    // 4-way unroll for memory-level parallelism on the random gathers
    for (; e + 4 <= end; e += 4) {
        int   s0 = g_src[e],     s1 = g_src[e + 1], s2 = g_src[e + 2], s3 = g_src[e + 3];
        float w0 = g_w[e],       w1 = g_w[e + 1],   w2 = g_w[e + 2],   w3 = g_w[e + 3];
        const float* p0 = X + (size_t)s0 * F + f0;
        const float* p1 = X + (size_t)s1 * F + f0;
        const float* p2 = X + (size_t)s2 * F + f0;
        const float* p3 = X + (size_t)s3 * F + f0;
        if (V == 4) { fmaV4(acc, p0, w0); fmaV4(acc, p1, w1); fmaV4(acc, p2, w2); fmaV4(acc, p3, w3); }
        else        { fmaV2(acc, p0, w0); fmaV2(acc, p1, w1); fmaV2(acc, p2, w2); fmaV2(acc, p3, w3); }
    }
    for (; e < end; ++e) {
        int s = g_src[e];
        float w = g_w[e];
        const float* p = X + (size_t)s * F + f0;
        if (V == 4) fmaV4(acc, p, w); else fmaV2(acc, p, w);
    }

    float dn = g_dinv[wid];
    {   // self loop: + dinv[c] * X[c]
        const float* p = X + (size_t)wid * F + f0;
        if (V == 4) fmaV4(acc, p, dn); else fmaV2(acc, p, dn);
    }
    const float* bp = (F == 128 && f0 >= 64) ? (bhi + f0 - 64) : (blo + f0);
#pragma unroll
    for (int v = 0; v < V; v++) acc[v] = acc[v] * dn + bp[v];

    float* yp = Y + (size_t)wid * F + f0;
    if (V == 4) *reinterpret_cast<float4*>(yp) = make_float4(acc[0], acc[1], acc[2], acc[3]);
    else        *reinterpret_cast<float2*>(yp) = make_float2(acc[0], acc[1]);
}

// ============================ launch ============================

extern "C" void kernel_launch(void* const* d_in, const int* in_sizes, int n_in,
                              void* d_out, int out_size) {
    const float* latent = (const float*)d_in[0];
    const float* cond   = (const float*)d_in[1];
    const int*   edge   = (const int*)  d_in[2];
    const float* W1 = (const float*)d_in[3];
    const float* b1 = (const float*)d_in[4];
    const float* W2 = (const float*)d_in[5];
    const float* b2 = (const float*)d_in[6];
    const float* W3 = (const float*)d_in[7];
    const float* b3 = (const float*)d_in[8];
    const float* W4 = (const float*)d_in[9];
    const float* b4 = (const float*)d_in[10];

    const int n = in_sizes[0] / 64;      // 100000
    const int E = in_sizes[2] / 2;       // 1600000
    const int* row = edge;
    const int* col = edge + E;

    static float *pX = nullptr, *pH = nullptr, *pT = nullptr, *pH2 = nullptr;
    if (!pX) {
        cudaGetSymbolAddress((void**)&pX,  g_X);
        cudaGetSymbolAddress((void**)&pH,  g_H);
        cudaGetSymbolAddress((void**)&pT,  g_T);
        cudaGetSymbolAddress((void**)&pH2, g_H2);
    }

    const int TB = 256;
    const int gN  = (n + TB - 1) / TB;
    const int gE  = (E + TB - 1) / TB;
    const int nbS = (n + 1023) / 1024;           // scan blocks (<= 1024)
    const int gN1 = (n + 1 + TB - 1) / TB;
    const int gW  = (n + 7) / 8;                 // 8 warps/block, warp per node

    // graph structure (shared by all 4 convs)
    k_zero<<<gN, TB>>>(n);
    k_hist<<<gE, TB>>>(col, E);
    k_scan_local<<<nbS, 1024>>>(n);
    k_scan_bsum<<<1, 1024>>>(nbS);
    k_scan_add<<<gN1, TB>>>(n, E);
    k_fill<<<gE, TB>>>(row, col, E);

    // layer 1+2 fused: X = [latent@W1 | cond@W2]; H = A·X + [b1|b2]
    k_gemm_fused<<<gN, TB>>>(latent, cond, W1, W2, pX, n);
    k_agg<128><<<gW, TB>>>(pX, pH, b1, b2, n);

    // layer 3: T = H@W3; H2 = A·T + b3
    k_gemm64<128><<<gN, TB>>>(pH, W3, pT, n);
    k_agg<64><<<gW, TB>>>(pT, pH2, b3, b3, n);

    // layer 4: T = H2@W4; out = A·T + b4
    k_gemm64<64><<<gN, TB>>>(pH2, W4, pT, n);
    k_agg<64><<<gW, TB>>>(pT, (float*)d_out, b4, b4, n);
}

// round 3
// speedup vs baseline: 1.1610x; 1.1610x over previous
#include <cuda_runtime.h>

// ===== static scratch (allocation-free rule: __device__ globals) =====
#define N_MAX 100352
#define E_MAX 1700032

__device__ int   g_cnt[N_MAX];
__device__ int   g_fill[N_MAX];      // running insert cursor (preinit to g_off)
__device__ int   g_off[N_MAX + 1];
__device__ int   g_bsum[1024];
__device__ float g_dinv[N_MAX];
__device__ int2  g_e[E_MAX];         // {src, __float_as_int(dinv[src])}

__device__ float g_a1[N_MAX];        // P·1
__device__ float g_a2[N_MAX];        // P²·1
__device__ float g_U[96 * 64];       // [W1@W3_top ; W2@W3_bot]
__device__ float g_c4[64];           // ([b1|b2]@W3)@W4
__device__ float g_e4[64];           // b3@W4
__device__ float g_f4[64];           // b4

__device__ float g_Y1[(size_t)N_MAX * 96];   // P·[L|C]
__device__ float g_T [(size_t)N_MAX * 64];   // Y1@U
__device__ float g_Y2[(size_t)N_MAX * 64];   // P·T
__device__ float g_Y3[(size_t)N_MAX * 64];   // P²·T

// ===== packed fp32x2 helpers (sm_103a) =====
__device__ __forceinline__ unsigned long long ffma2(unsigned long long a,
                                                    unsigned long long b,
                                                    unsigned long long c) {
    unsigned long long d;
    asm("fma.rn.f32x2 %0, %1, %2, %3;" : "=l"(d) : "l"(a), "l"(b), "l"(c));
    return d;
}
__device__ __forceinline__ unsigned long long pack2(float x) {
    unsigned long long d;
    asm("mov.b64 %0, {%1, %1};" : "=l"(d) : "r"(__float_as_uint(x)));
    return d;
}
__device__ __forceinline__ float2 unpack2(unsigned long long v) {
    unsigned int lo, hi;
    asm("mov.b64 {%0, %1}, %2;" : "=r"(lo), "=r"(hi) : "l"(v));
    return make_float2(__uint_as_float(lo), __uint_as_float(hi));
}

// ============================ graph construction ============================

__global__ void k_zero(int n) {
    int i = blockIdx.x * blockDim.x + threadIdx.x;
    if (i < n) g_cnt[i] = 0;
}

__global__ void k_hist(const int* __restrict__ col, int E) {
    int e = blockIdx.x * blockDim.x + threadIdx.x;
    if (e < E) atomicAdd(&g_cnt[col[e]], 1);
}

__global__ void k_scan_local(int n) {
    __shared__ int s[1024];
    int tid = threadIdx.x;
    int i = blockIdx.x * 1024 + tid;
    int v = (i < n) ? g_cnt[i] : 0;
    s[tid] = v;
    __syncthreads();
    for (int d = 1; d < 1024; d <<= 1) {
        int t = (tid >= d) ? s[tid - d] : 0;
        __syncthreads();
        s[tid] += t;
        __syncthreads();
    }
    if (i < n) g_off[i] = s[tid] - v;
    if (tid == 1023) g_bsum[blockIdx.x] = s[1023];
}

__global__ void k_scan_bsum(int nb) {
    __shared__ int s[1024];
    int tid = threadIdx.x;
    int v = (tid < nb) ? g_bsum[tid] : 0;
    s[tid] = v;
    __syncthreads();
    for (int d = 1; d < 1024; d <<= 1) {
        int t = (tid >= d) ? s[tid - d] : 0;
        __syncthreads();
        s[tid] += t;
        __syncthreads();
    }
    if (tid < nb) g_bsum[tid] = s[tid] - v;
}

__global__ void k_scan_add(int n, int E) {
    int i = blockIdx.x * blockDim.x + threadIdx.x;
    if (i < n) {
        int o = g_off[i] + g_bsum[i >> 10];
        g_off[i]  = o;
        g_fill[i] = o;                             // fill cursor starts at offset
        g_dinv[i] = rsqrtf((float)(g_cnt[i] + 1)); // +1 self loop
    }
    if (i == n) g_off[n] = E;
}

__global__ void k_fill(const int* __restrict__ row, const int* __restrict__ col, int E) {
    int e = blockIdx.x * blockDim.x + threadIdx.x;
    if (e < E) {
        int r = row[e], c = col[e];
        int pos = atomicAdd(&g_fill[c], 1);
        g_e[pos] = make_int2(r, __float_as_int(g_dinv[r]));
    }
}

// ============================ weight precompute ============================
// U[0:64]  = W1 @ W3[0:64,:],  U[64:96] = W2 @ W3[64:128,:]
// c4 = ([b1|b2]@W3)@W4, e4 = b3@W4, f4 = b4
__global__ void k_wprep(const float* __restrict__ W1, const float* __restrict__ W2,
                        const float* __restrict__ W3, const float* __restrict__ W4,
                        const float* __restrict__ b1, const float* __restrict__ b2,
                        const float* __restrict__ b3, const float* __restrict__ b4) {
    __shared__ float sA[64 * 64], sB[64 * 64], sc3[64];
    int tid = threadIdx.x;

    // phase 1: W1 @ W3_top
    for (int i = tid; i < 64 * 64; i += 256) { sA[i] = W1[i]; sB[i] = W3[i]; }
    __syncthreads();
    for (int o = tid; o < 64 * 64; o += 256) {
        int k = o >> 6, j = o & 63;
        float s = 0.f;
        for (int m = 0; m < 64; m++) s += sA[k * 64 + m] * sB[m * 64 + j];
        g_U[o] = s;
    }
    if (tid < 64) {
        float s = 0.f;
        for (int m = 0; m < 64; m++) s += b1[m] * sB[m * 64 + tid];
        sc3[tid] = s;
    }
    __syncthreads();

    // phase 2: W2 @ W3_bot
    for (int i = tid; i < 32 * 64; i += 256) sA[i] = W2[i];
    for (int i = tid; i < 64 * 64; i += 256) sB[i] = W3[64 * 64 + i];
    __syncthreads();
    for (int o = tid; o < 32 * 64; o += 256) {
        int k = o >> 6, j = o & 63;
        float s = 0.f;
        for (int m = 0; m < 64; m++) s += sA[k * 64 + m] * sB[m * 64 + j];
        g_U[64 * 64 + o] = s;
    }
    if (tid < 64) {
        float s = sc3[tid];
        for (int m = 0; m < 64; m++) s += b2[m] * sB[m * 64 + tid];
        sc3[tid] = s;
    }
    __syncthreads();

    // phase 3: project through W4
    for (int i = tid; i < 64 * 64; i += 256) sA[i] = W4[i];
    __syncthreads();
    if (tid < 64) {
        float s = 0.f, t = 0.f;
        for (int m = 0; m < 64; m++) {
            s += sc3[m] * sA[m * 64 + tid];
            t += b3[m]  * sA[m * 64 + tid];
        }
        g_c4[tid] = s; g_e4[tid] = t; g_f4[tid] = b4[tid];
    }
}

// ============================ aggregation (pure P) ============================
// Y[c] = dinv[c] * ( sum_e dinv[src]*x[src] + dinv[c]*x[c] )

__device__ __forceinline__ void fmaV4(float* acc, const float* p, float w) {
    float4 x = *reinterpret_cast<const float4*>(p);
    acc[0] += w * x.x; acc[1] += w * x.y; acc[2] += w * x.z; acc[3] += w * x.w;
}
__device__ __forceinline__ void fmaV2(float* acc, const float* p, float w) {
    float2 x = *reinterpret_cast<const float2*>(p);
    acc[0] += w * x.x; acc[1] += w * x.y;
}

// first pass: gather raw [latent(64)|cond(32)] -> g_Y1 (stride 96); also a1.
__global__ void k_agg96(const float* __restrict__ latent, const float* __restrict__ cond,
                        int n) {
    int wid  = (blockIdx.x * blockDim.x + threadIdx.x) >> 5;
    int lane = threadIdx.x & 31;
    if (wid >= n) return;

    int e = g_off[wid];
    const int end = g_off[wid + 1];
    float dn = g_dinv[wid];

    if (lane < 24) {
        const int f0 = lane * 4;
        const bool isL = (f0 < 64);
        float acc[4] = {0.f, 0.f, 0.f, 0.f};
        float sw = 0.f;

        for (; e + 4 <= end; e += 4) {
            int2 e0 = g_e[e], e1 = g_e[e + 1], e2 = g_e[e + 2], e3 = g_e[e + 3];
            float w0 = __int_as_float(e0.y), w1 = __int_as_float(e1.y);
            float w2 = __int_as_float(e2.y), w3 = __int_as_float(e3.y);
            const float* p0 = isL ? (latent + (size_t)e0.x * 64 + f0) : (cond + (size_t)e0.x * 32 + f0 - 64);
            const float* p1 = isL ? (latent + (size_t)e1.x * 64 + f0) : (cond + (size_t)e1.x * 32 + f0 - 64);
            const float* p2 = isL ? (latent + (size_t)e2.x * 64 + f0) : (cond + (size_t)e2.x * 32 + f0 - 64);
            const float* p3 = isL ? (latent + (size_t)e3.x * 64 + f0) : (cond + (size_t)e3.x * 32 + f0 - 64);
            fmaV4(acc, p0, w0); fmaV4(acc, p1, w1); fmaV4(acc, p2, w2); fmaV4(acc, p3, w3);
            sw += w0 + w1 + w2 + w3;
        }
        for (; e < end; ++e) {
            int2 ev = g_e[e];
            float w = __int_as_float(ev.y);
            const float* p = isL ? (latent + (size_t)ev.x * 64 + f0) : (cond + (size_t)ev.x * 32 + f0 - 64);
            fmaV4(acc, p, w);
            sw += w;
        }
        // self loop
        const float* ps = isL ? (latent + (size_t)wid * 64 + f0) : (cond + (size_t)wid * 32 + f0 - 64);
        fmaV4(acc, ps, dn);

        float* yp = g_Y1 + (size_t)wid * 96 + f0;
        *reinterpret_cast<float4*>(yp) =
            make_float4(acc[0] * dn, acc[1] * dn, acc[2] * dn, acc[3] * dn);
        if (lane == 0) g_a1[wid] = dn * (sw + dn);
    }
}

// 64-wide pure aggregation
__global__ void k_agg64(const float* __restrict__ X, float* __restrict__ Y, int n) {
    int wid  = (blockIdx.x * blockDim.x + threadIdx.x) >> 5;
    int lane = threadIdx.x & 31;
    if (wid >= n) return;

    const int f0 = lane * 2;
    int e = g_off[wid];
    const int end = g_off[wid + 1];
    float acc[2] = {0.f, 0.f};

    for (; e + 4 <= end; e += 4) {
        int2 e0 = g_e[e], e1 = g_e[e + 1], e2 = g_e[e + 2], e3 = g_e[e + 3];
        fmaV2(acc, X + (size_t)e0.x * 64 + f0, __int_as_float(e0.y));
        fmaV2(acc, X + (size_t)e1.x * 64 + f0, __int_as_float(e1.y));
        fmaV2(acc, X + (size_t)e2.x * 64 + f0, __int_as_float(e2.y));
        fmaV2(acc, X + (size_t)e3.x * 64 + f0, __int_as_float(e3.y));
    }
    for (; e < end; ++e) {
        int2 ev = g_e[e];
        fmaV2(acc, X + (size_t)ev.x * 64 + f0, __int_as_float(ev.y));
    }
    float dn = g_dinv[wid];
    fmaV2(acc, X + (size_t)wid * 64 + f0, dn);
    *reinterpret_cast<float2*>(Y + (size_t)wid * 64 + f0) =
        make_float2(acc[0] * dn, acc[1] * dn);
}

// a2 = P · a1  (1-wide; lanes split the edge list, shuffle-reduce)
__global__ void k_agg_a2(int n) {
    int wid  = (blockIdx.x * blockDim.x + threadIdx.x) >> 5;
    int lane = threadIdx.x & 31;
    if (wid >= n) return;
    int beg = g_off[wid], end = g_off[wid + 1];
    float acc = 0.f;
    for (int e = beg + lane; e < end; e += 32) {
        int2 ev = g_e[e];
        acc += __int_as_float(ev.y) * g_a1[ev.x];
    }
    for (int d = 16; d; d >>= 1) acc += __shfl_down_sync(0xffffffffu, acc, d);
    if (lane == 0) {
        float dn = g_dinv[wid];
        g_a2[wid] = dn * (acc + dn * g_a1[wid]);
    }
}

// ============================ packed-fp32 GEMM ============================
// Y[n,64] = A[n,FIN] @ W[FIN,64]  (+ rank-1 bias terms when RANK1)
template <int FIN, bool RANK1>
__global__ void k_gemm64x(const float* __restrict__ A, const float* __restrict__ Wg,
                          float* __restrict__ Y, int n) {
    __shared__ __align__(16) float sW[FIN * 64];
    __shared__ float sc[64], se[64], sf[64];
    for (int i = threadIdx.x; i < FIN * 64; i += blockDim.x) sW[i] = Wg[i];
    if (RANK1 && threadIdx.x < 64) {
        sc[threadIdx.x] = g_c4[threadIdx.x];
        se[threadIdx.x] = g_e4[threadIdx.x];
        sf[threadIdx.x] = g_f4[threadIdx.x];
    }
    __syncthreads();
    int node = blockIdx.x * blockDim.x + threadIdx.x;
    if (node >= n) return;

    unsigned long long acc[32];
#pragma unroll
    for (int j = 0; j < 32; j++) acc[j] = 0ull;

    const float* arow = A + (size_t)node * FIN;
#pragma unroll 2
    for (int k = 0; k < FIN; k += 4) {
        float4 av = *reinterpret_cast<const float4*>(arow + k);
        unsigned long long p0 = pack2(av.x), p1 = pack2(av.y);
        unsigned long long p2 = pack2(av.z), p3 = pack2(av.w);
        const ulonglong2* w0 = reinterpret_cast<const ulonglong2*>(sW + (k + 0) * 64);
        const ulonglong2* w1 = reinterpret_cast<const ulonglong2*>(sW + (k + 1) * 64);
        const ulonglong2* w2 = reinterpret_cast<const ulonglong2*>(sW + (k + 2) * 64);
        const ulonglong2* w3 = reinterpret_cast<const ulonglong2*>(sW + (k + 3) * 64);
#pragma unroll
        for (int j = 0; j < 16; j++) {
            ulonglong2 q;
            q = w0[j]; acc[2*j] = ffma2(p0, q.x, acc[2*j]); acc[2*j+1] = ffma2(p0, q.y, acc[2*j+1]);
            q = w1[j]; acc[2*j] = ffma2(p1, q.x, acc[2*j]); acc[2*j+1] = ffma2(p1, q.y, acc[2*j+1]);
            q = w2[j]; acc[2*j] = ffma2(p2, q.x, acc[2*j]); acc[2*j+1] = ffma2(p2, q.y, acc[2*j+1]);
            q = w3[j]; acc[2*j] = ffma2(p3, q.x, acc[2*j]); acc[2*j+1] = ffma2(p3, q.y, acc[2*j+1]);
        }
    }

    float av1 = 0.f, av2 = 0.f;
    if (RANK1) { av1 = g_a1[node]; av2 = g_a2[node]; }
    float* yrow = Y + (size_t)node * 64;
#pragma unroll
    for (int j = 0; j < 16; j++) {
        float2 lo = unpack2(acc[2*j]);
        float2 hi = unpack2(acc[2*j+1]);
        float4 o = make_float4(lo.x, lo.y, hi.x, hi.y);
        if (RANK1) {
            int c0 = 4 * j;
            o.x += av2 * sc[c0+0] + av1 * se[c0+0] + sf[c0+0];
            o.y += av2 * sc[c0+1] + av1 * se[c0+1] + sf[c0+1];
            o.z += av2 * sc[c0+2] + av1 * se[c0+2] + sf[c0+2];
            o.w += av2 * sc[c0+3] + av1 * se[c0+3] + sf[c0+3];
        }
        *reinterpret_cast<float4*>(yrow + 4 * j) = o;
    }
}

// ============================ launch ============================

extern "C" void kernel_launch(void* const* d_in, const int* in_sizes, int n_in,
                              void* d_out, int out_size) {
    const float* latent = (const float*)d_in[0];
    const float* cond   = (const float*)d_in[1];
    const int*   edge   = (const int*)  d_in[2];
    const float* W1 = (const float*)d_in[3];
    const float* b1 = (const float*)d_in[4];
    const float* W2 = (const float*)d_in[5];
    const float* b2 = (const float*)d_in[6];
    const float* W3 = (const float*)d_in[7];
    const float* b3 = (const float*)d_in[8];
    const float* W4 = (const float*)d_in[9];
    const float* b4 = (const float*)d_in[10];

    const int n = in_sizes[0] / 64;      // 100000
    const int E = in_sizes[2] / 2;       // 1600000
    const int* row = edge;
    const int* col = edge + E;

    static float *pY1 = nullptr, *pT = nullptr, *pY2 = nullptr, *pY3 = nullptr, *pU = nullptr;
    if (!pY1) {
        cudaGetSymbolAddress((void**)&pY1, g_Y1);
        cudaGetSymbolAddress((void**)&pT,  g_T);
        cudaGetSymbolAddress((void**)&pY2, g_Y2);
        cudaGetSymbolAddress((void**)&pY3, g_Y3);
        cudaGetSymbolAddress((void**)&pU,  g_U);
    }

    const int TB  = 256;
    const int gN  = (n + TB - 1) / TB;
    const int gE  = (E + TB - 1) / TB;
    const int nbS = (n + 1023) / 1024;
    const int gN1 = (n + 1 + TB - 1) / TB;
    const int gW  = (n + 7) / 8;   // 8 warps/block

    // ---- graph structure ----
    k_zero<<<gN, TB>>>(n);
    k_hist<<<gE, TB>>>(col, E);
    k_scan_local<<<nbS, 1024>>>(n);
    k_scan_bsum<<<1, 1024>>>(nbS);
    k_scan_add<<<gN1, TB>>>(n, E);
    k_fill<<<gE, TB>>>(row, col, E);

    // ---- collapsed weights / bias vectors ----
    k_wprep<<<1, 256>>>(W1, W2, W3, W4, b1, b2, b3, b4);

    // ---- Y1 = P·[L|C] (also a1 = P·1) ----
    k_agg96<<<gW, TB>>>(latent, cond, n);
    // ---- a2 = P·a1 ----
    k_agg_a2<<<gW, TB>>>(n);
    // ---- T = Y1 @ U ----
    k_gemm64x<96, false><<<gN, TB>>>(pY1, pU, pT, n);
    // ---- Y2 = P·T ; Y3 = P·Y2 ----
    k_agg64<<<gW, TB>>>(pT,  pY2, n);
    k_agg64<<<gW, TB>>>(pY2, pY3, n);
    // ---- out = Y3@W4 + a2·c4 + a1·e4 + f4 ----
    k_gemm64x<64, true><<<gN, TB>>>(pY3, W4, (float*)d_out, n);
}

// round 4
// speedup vs baseline: 1.2815x; 1.1038x over previous
#include <cuda_runtime.h>
#include <cuda_fp16.h>

// ===== static scratch (allocation-free rule: __device__ globals) =====
#define N_MAX 100352
#define E_MAX 1700032

__device__ int   g_cnt[N_MAX];
__device__ int   g_fill[N_MAX];
__device__ int   g_off[N_MAX + 1];
__device__ int   g_bsum[1024];
__device__ float g_dinv[N_MAX];
__device__ int2  g_e[E_MAX];         // {src, __float_as_int(dinv[src])}

__device__ float g_a1[N_MAX];        // P·1
__device__ float g_a2[N_MAX];        // P²·1
__device__ float g_U[96 * 64];       // [W1@W3_top ; W2@W3_bot]
__device__ float g_c4[64];           // ([b1|b2]@W3)@W4
__device__ float g_e4[64];           // b3@W4
__device__ float g_f4[64];           // b4

__device__ __align__(16) __half g_LC [(size_t)N_MAX * 96];  // fp16 [latent|cond]
__device__ float                g_Y1 [(size_t)N_MAX * 96];  // P·[L|C] (fp32)
__device__ __align__(16) __half g_Th [(size_t)N_MAX * 64];  // Y1@U (fp16)
__device__ __align__(16) __half g_Y2h[(size_t)N_MAX * 64];  // P·T (fp16)
__device__ float                g_Y3 [(size_t)N_MAX * 64];  // P²·T (fp32)

// ===== packed fp32x2 helpers (sm_103a) =====
__device__ __forceinline__ unsigned long long ffma2(unsigned long long a,
                                                    unsigned long long b,
                                                    unsigned long long c) {
    unsigned long long d;
    asm("fma.rn.f32x2 %0, %1, %2, %3;" : "=l"(d) : "l"(a), "l"(b), "l"(c));
    return d;
}
__device__ __forceinline__ unsigned long long pack2(float x) {
    unsigned long long d;
    asm("mov.b64 %0, {%1, %1};" : "=l"(d) : "r"(__float_as_uint(x)));
    return d;
}
__device__ __forceinline__ float2 unpack2(unsigned long long v) {
    unsigned int lo, hi;
    asm("mov.b64 {%0, %1}, %2;" : "=r"(lo), "=r"(hi) : "l"(v));
    return make_float2(__uint_as_float(lo), __uint_as_float(hi));
}

// ============================ init: zero counters + fp16 convert ============================

__global__ void k_init(const float* __restrict__ latent, const float* __restrict__ cond, int n) {
    int idx = blockIdx.x * blockDim.x + threadIdx.x;
    if (idx < n) g_cnt[idx] = 0;
    if (idx < n * 24) {                 // 4 features per thread, 24 chunks per node
        int row = idx / 24;
        int c0  = (idx % 24) * 4;
        float4 v;
        if (c0 < 64) v = *reinterpret_cast<const float4*>(latent + (size_t)row * 64 + c0);
        else         v = *reinterpret_cast<const float4*>(cond   + (size_t)row * 32 + (c0 - 64));
        __half2 h01 = __floats2half2_rn(v.x, v.y);
        __half2 h23 = __floats2half2_rn(v.z, v.w);
        uint2 u = make_uint2(*reinterpret_cast<unsigned*>(&h01),
                             *reinterpret_cast<unsigned*>(&h23));
        *reinterpret_cast<uint2*>(g_LC + (size_t)row * 96 + c0) = u;
    }
}

// ============================ graph construction ============================

__global__ void k_hist(const int* __restrict__ col, int E) {
    int e = blockIdx.x * blockDim.x + threadIdx.x;
    if (e < E) atomicAdd(&g_cnt[col[e]], 1);
}

__global__ void k_scan_local(int n) {
    __shared__ int s[1024];
    int tid = threadIdx.x;
    int i = blockIdx.x * 1024 + tid;
    int v = (i < n) ? g_cnt[i] : 0;
    s[tid] = v;
    __syncthreads();
    for (int d = 1; d < 1024; d <<= 1) {
        int t = (tid >= d) ? s[tid - d] : 0;
        __syncthreads();
        s[tid] += t;
        __syncthreads();
    }
    if (i < n) g_off[i] = s[tid] - v;
    if (tid == 1023) g_bsum[blockIdx.x] = s[1023];
}

__global__ void k_scan_bsum(int nb) {
    __shared__ int s[1024];
    int tid = threadIdx.x;
    int v = (tid < nb) ? g_bsum[tid] : 0;
    s[tid] = v;
    __syncthreads();
    for (int d = 1; d < 1024; d <<= 1) {
        int t = (tid >= d) ? s[tid - d] : 0;
        __syncthreads();
        s[tid] += t;
        __syncthreads();
    }
    if (tid < nb) g_bsum[tid] = s[tid] - v;
}

__global__ void k_scan_add(int n, int E) {
    int i = blockIdx.x * blockDim.x + threadIdx.x;
    if (i < n) {
        int o = g_off[i] + g_bsum[i >> 10];
        g_off[i]  = o;
        g_fill[i] = o;
        g_dinv[i] = rsqrtf((float)(g_cnt[i] + 1));
    }
    if (i == n) g_off[n] = E;
}

__global__ void k_fill(const int* __restrict__ row, const int* __restrict__ col, int E) {
    int e = blockIdx.x * blockDim.x + threadIdx.x;
    if (e < E) {
        int r = row[e], c = col[e];
        int pos = atomicAdd(&g_fill[c], 1);
        g_e[pos] = make_int2(r, __float_as_int(g_dinv[r]));
    }
}

// ============================ weight precompute ============================
__global__ void k_wprep(const float* __restrict__ W1, const float* __restrict__ W2,
                        const float* __restrict__ W3, const float* __restrict__ W4,
                        const float* __restrict__ b1, const float* __restrict__ b2,
                        const float* __restrict__ b3, const float* __restrict__ b4) {
    __shared__ float sA[64 * 64], sB[64 * 64], sc3[64];
    int tid = threadIdx.x;

    for (int i = tid; i < 64 * 64; i += 256) { sA[i] = W1[i]; sB[i] = W3[i]; }
    __syncthreads();
    for (int o = tid; o < 64 * 64; o += 256) {
        int k = o >> 6, j = o & 63;
        float s = 0.f;
        for (int m = 0; m < 64; m++) s += sA[k * 64 + m] * sB[m * 64 + j];
        g_U[o] = s;
    }
    if (tid < 64) {
        float s = 0.f;
        for (int m = 0; m < 64; m++) s += b1[m] * sB[m * 64 + tid];
        sc3[tid] = s;
    }
    __syncthreads();

    for (int i = tid; i < 32 * 64; i += 256) sA[i] = W2[i];
    for (int i = tid; i < 64 * 64; i += 256) sB[i] = W3[64 * 64 + i];
    __syncthreads();
    for (int o = tid; o < 32 * 64; o += 256) {
        int k = o >> 6, j = o & 63;
        float s = 0.f;
        for (int m = 0; m < 64; m++) s += sA[k * 64 + m] * sB[m * 64 + j];
        g_U[64 * 64 + o] = s;
    }
    if (tid < 64) {
        float s = sc3[tid];
        for (int m = 0; m < 64; m++) s += b2[m] * sB[m * 64 + tid];
        sc3[tid] = s;
    }
    __syncthreads();

    for (int i = tid; i < 64 * 64; i += 256) sA[i] = W4[i];
    __syncthreads();
    if (tid < 64) {
        float s = 0.f, t = 0.f;
        for (int m = 0; m < 64; m++) {
            s += sc3[m] * sA[m * 64 + tid];
            t += b3[m]  * sA[m * 64 + tid];
        }
        g_c4[tid] = s; g_e4[tid] = t; g_f4[tid] = b4[tid];
    }
}

// ============================ aggregation (pure P, fp16 sources) ============================

__device__ __forceinline__ void fmaH4(float* acc, const __half* p, float w) {
    uint2 u = *reinterpret_cast<const uint2*>(p);
    __half2 h01 = *reinterpret_cast<__half2*>(&u.x);
    __half2 h23 = *reinterpret_cast<__half2*>(&u.y);
    float2 f01 = __half22float2(h01), f23 = __half22float2(h23);
    acc[0] += w * f01.x; acc[1] += w * f01.y;
    acc[2] += w * f23.x; acc[3] += w * f23.y;
}
__device__ __forceinline__ void fmaH2(float* acc, const __half* p, float w) {
    __half2 h = *reinterpret_cast<const __half2*>(p);
    float2 f = __half22float2(h);
    acc[0] += w * f.x; acc[1] += w * f.y;
}

// first pass: gather fp16 LC (stride 96) -> g_Y1 fp32 (stride 96); also a1.
__global__ void k_agg96h(int n) {
    int wid  = (blockIdx.x * blockDim.x + threadIdx.x) >> 5;
    int lane = threadIdx.x & 31;
    if (wid >= n) return;

    int e = g_off[wid];
    const int end = g_off[wid + 1];
    float dn = g_dinv[wid];

    if (lane < 24) {
        const int f0 = lane * 4;
        float acc[4] = {0.f, 0.f, 0.f, 0.f};
        float sw = 0.f;

        for (; e + 4 <= end; e += 4) {
            int2 e0 = g_e[e], e1 = g_e[e + 1], e2 = g_e[e + 2], e3 = g_e[e + 3];
            float w0 = __int_as_float(e0.y), w1 = __int_as_float(e1.y);
            float w2 = __int_as_float(e2.y), w3 = __int_as_float(e3.y);
            fmaH4(acc, g_LC + (size_t)e0.x * 96 + f0, w0);
            fmaH4(acc, g_LC + (size_t)e1.x * 96 + f0, w1);
            fmaH4(acc, g_LC + (size_t)e2.x * 96 + f0, w2);
            fmaH4(acc, g_LC + (size_t)e3.x * 96 + f0, w3);
            sw += w0 + w1 + w2 + w3;
        }
        for (; e < end; ++e) {
            int2 ev = g_e[e];
            float w = __int_as_float(ev.y);
            fmaH4(acc, g_LC + (size_t)ev.x * 96 + f0, w);
            sw += w;
        }
        fmaH4(acc, g_LC + (size_t)wid * 96 + f0, dn);  // self loop

        *reinterpret_cast<float4*>(g_Y1 + (size_t)wid * 96 + f0) =
            make_float4(acc[0] * dn, acc[1] * dn, acc[2] * dn, acc[3] * dn);
        if (lane == 0) g_a1[wid] = dn * (sw + dn);
    }
}

// 64-wide aggregation: fp16 in, fp16 or fp32 out
template <bool OUTH>
__global__ void k_agg64h(const __half* __restrict__ X, void* __restrict__ Yv, int n) {
    int wid  = (blockIdx.x * blockDim.x + threadIdx.x) >> 5;
    int lane = threadIdx.x & 31;
    if (wid >= n) return;

    const int f0 = lane * 2;
    int e = g_off[wid];
    const int end = g_off[wid + 1];
    float acc[2] = {0.f, 0.f};

    for (; e + 4 <= end; e += 4) {
        int2 e0 = g_e[e], e1 = g_e[e + 1], e2 = g_e[e + 2], e3 = g_e[e + 3];
        fmaH2(acc, X + (size_t)e0.x * 64 + f0, __int_as_float(e0.y));
        fmaH2(acc, X + (size_t)e1.x * 64 + f0, __int_as_float(e1.y));
        fmaH2(acc, X + (size_t)e2.x * 64 + f0, __int_as_float(e2.y));
        fmaH2(acc, X + (size_t)e3.x * 64 + f0, __int_as_float(e3.y));
    }
    for (; e < end; ++e) {
        int2 ev = g_e[e];
        fmaH2(acc, X + (size_t)ev.x * 64 + f0, __int_as_float(ev.y));
    }
    float dn = g_dinv[wid];
    fmaH2(acc, X + (size_t)wid * 64 + f0, dn);
    if (OUTH) {
        __half2 h = __floats2half2_rn(acc[0] * dn, acc[1] * dn);
        *reinterpret_cast<__half2*>((__half*)Yv + (size_t)wid * 64 + f0) = h;
    } else {
        *reinterpret_cast<float2*>((float*)Yv + (size_t)wid * 64 + f0) =
            make_float2(acc[0] * dn, acc[1] * dn);
    }
}

// a2 = P · a1
__global__ void k_agg_a2(int n) {
    int wid  = (blockIdx.x * blockDim.x + threadIdx.x) >> 5;
    int lane = threadIdx.x & 31;
    if (wid >= n) return;
    int beg = g_off[wid], end = g_off[wid + 1];
    float acc = 0.f;
    for (int e = beg + lane; e < end; e += 32) {
        int2 ev = g_e[e];
        acc += __int_as_float(ev.y) * g_a1[ev.x];
    }
    for (int d = 16; d; d >>= 1) acc += __shfl_down_sync(0xffffffffu, acc, d);
    if (lane == 0) {
        float dn = g_dinv[wid];
        g_a2[wid] = dn * (acc + dn * g_a1[wid]);
    }
}

// ============================ packed-fp32 GEMM ============================
// Y[n,64] = A[n,FIN] @ W[FIN,64]; optional rank-1 bias terms; optional fp16 output.
template <int FIN, bool RANK1, bool OUTH>
__global__ void k_gemm64x(const float* __restrict__ A, const float* __restrict__ Wg,
                          void* __restrict__ Yv, int n) {
    __shared__ __align__(16) float sW[FIN * 64];
    __shared__ float sc[64], se[64], sf[64];
    for (int i = threadIdx.x; i < FIN * 64; i += blockDim.x) sW[i] = Wg[i];
    if (RANK1 && threadIdx.x < 64) {
        sc[threadIdx.x] = g_c4[threadIdx.x];
        se[threadIdx.x] = g_e4[threadIdx.x];
        sf[threadIdx.x] = g_f4[threadIdx.x];
    }
    __syncthreads();
    int node = blockIdx.x * blockDim.x + threadIdx.x;
    if (node >= n) return;

    unsigned long long acc[32];
#pragma unroll
    for (int j = 0; j < 32; j++) acc[j] = 0ull;

    const float* arow = A + (size_t)node * FIN;
#pragma unroll 2
    for (int k = 0; k < FIN; k += 4) {
        float4 av = *reinterpret_cast<const float4*>(arow + k);
        unsigned long long p0 = pack2(av.x), p1 = pack2(av.y);
        unsigned long long p2 = pack2(av.z), p3 = pack2(av.w);
        const ulonglong2* w0 = reinterpret_cast<const ulonglong2*>(sW + (k + 0) * 64);
        const ulonglong2* w1 = reinterpret_cast<const ulonglong2*>(sW + (k + 1) * 64);
        const ulonglong2* w2 = reinterpret_cast<const ulonglong2*>(sW + (k + 2) * 64);
        const ulonglong2* w3 = reinterpret_cast<const ulonglong2*>(sW + (k + 3) * 64);
#pragma unroll
        for (int j = 0; j < 16; j++) {
            ulonglong2 q;
            q = w0[j]; acc[2*j] = ffma2(p0, q.x, acc[2*j]); acc[2*j+1] = ffma2(p0, q.y, acc[2*j+1]);
            q = w1[j]; acc[2*j] = ffma2(p1, q.x, acc[2*j]); acc[2*j+1] = ffma2(p1, q.y, acc[2*j+1]);
            q = w2[j]; acc[2*j] = ffma2(p2, q.x, acc[2*j]); acc[2*j+1] = ffma2(p2, q.y, acc[2*j+1]);
            q = w3[j]; acc[2*j] = ffma2(p3, q.x, acc[2*j]); acc[2*j+1] = ffma2(p3, q.y, acc[2*j+1]);
        }
    }

    float av1 = 0.f, av2 = 0.f;
    if (RANK1) { av1 = g_a1[node]; av2 = g_a2[node]; }
#pragma unroll
    for (int j = 0; j < 16; j++) {
        float2 lo = unpack2(acc[2*j]);
        float2 hi = unpack2(acc[2*j+1]);
        float4 o = make_float4(lo.x, lo.y, hi.x, hi.y);
        if (RANK1) {
            int c0 = 4 * j;
            o.x += av2 * sc[c0+0] + av1 * se[c0+0] + sf[c0+0];
            o.y += av2 * sc[c0+1] + av1 * se[c0+1] + sf[c0+1];
            o.z += av2 * sc[c0+2] + av1 * se[c0+2] + sf[c0+2];
            o.w += av2 * sc[c0+3] + av1 * se[c0+3] + sf[c0+3];
        }
        if (OUTH) {
            __half2 h01 = __floats2half2_rn(o.x, o.y);
            __half2 h23 = __floats2half2_rn(o.z, o.w);
            uint2 u = make_uint2(*reinterpret_cast<unsigned*>(&h01),
                                 *reinterpret_cast<unsigned*>(&h23));
            *reinterpret_cast<uint2*>((__half*)Yv + (size_t)node * 64 + 4 * j) = u;
        } else {
            *reinterpret_cast<float4*>((float*)Yv + (size_t)node * 64 + 4 * j) = o;
        }
    }
}

// ============================ launch ============================

extern "C" void kernel_launch(void* const* d_in, const int* in_sizes, int n_in,
                              void* d_out, int out_size) {
    const float* latent = (const float*)d_in[0];
    const float* cond   = (const float*)d_in[1];
    const int*   edge   = (const int*)  d_in[2];
    const float* W1 = (const float*)d_in[3];
    const float* b1 = (const float*)d_in[4];
    const float* W2 = (const float*)d_in[5];
    const float* b2 = (const float*)d_in[6];
    const float* W3 = (const float*)d_in[7];
    const float* b3 = (const float*)d_in[8];
    const float* W4 = (const float*)d_in[9];
    const float* b4 = (const float*)d_in[10];

    const int n = in_sizes[0] / 64;      // 100000
    const int E = in_sizes[2] / 2;       // 1600000
    const int* row = edge;
    const int* col = edge + E;

    static float *pY1 = nullptr, *pY3 = nullptr, *pU = nullptr;
    static __half *pTh = nullptr, *pY2h = nullptr;
    if (!pY1) {
        cudaGetSymbolAddress((void**)&pY1,  g_Y1);
        cudaGetSymbolAddress((void**)&pY3,  g_Y3);
        cudaGetSymbolAddress((void**)&pU,   g_U);
        cudaGetSymbolAddress((void**)&pTh,  g_Th);
        cudaGetSymbolAddress((void**)&pY2h, g_Y2h);
    }

    const int TB  = 256;
    const int gI  = (n * 24 + TB - 1) / TB;
    const int gN  = (n + TB - 1) / TB;
    const int gE  = (E + TB - 1) / TB;
    const int nbS = (n + 1023) / 1024;
    const int gN1 = (n + 1 + TB - 1) / TB;
    const int gW  = (n + 7) / 8;   // 8 warps/block

    // ---- init: zero counters + fp16 convert inputs ----
    k_init<<<gI, TB>>>(latent, cond, n);
    // ---- graph structure ----
    k_hist<<<gE, TB>>>(col, E);
    k_scan_local<<<nbS, 1024>>>(n);
    k_scan_bsum<<<1, 1024>>>(nbS);
    k_scan_add<<<gN1, TB>>>(n, E);
    k_fill<<<gE, TB>>>(row, col, E);
    // ---- collapsed weights / bias vectors ----
    k_wprep<<<1, 256>>>(W1, W2, W3, W4, b1, b2, b3, b4);

    // ---- Y1 = P·[L|C] (fp16 gather), a1 ----
    k_agg96h<<<gW, TB>>>(n);
    // ---- a2 = P·a1 ----
    k_agg_a2<<<gW, TB>>>(n);
    // ---- T = Y1 @ U (fp16 out) ----
    k_gemm64x<96, false, true><<<gN, TB>>>(pY1, pU, pTh, n);
    // ---- Y2 = P·T (fp16) ; Y3 = P·Y2 (fp32) ----
    k_agg64h<true ><<<gW, TB>>>(pTh,  pY2h, n);
    k_agg64h<false><<<gW, TB>>>(pY2h, pY3,  n);
    // ---- out = Y3@W4 + a2·c4 + a1·e4 + f4 ----
    k_gemm64x<64, true, false><<<gN, TB>>>(pY3, W4, (float*)d_out, n);
}

// round 6
// speedup vs baseline: 1.4757x; 1.1515x over previous
#include <cuda_runtime.h>
#include <cuda_fp16.h>

// ===== static scratch (allocation-free rule: __device__ globals) =====
#define N_MAX 100352
#define E_MAX 1700032

__device__ int   g_cnt[N_MAX];
__device__ int   g_fill[N_MAX];
__device__ int   g_off[N_MAX + 1];
__device__ int   g_bsum[1024];
__device__ float g_dinv[N_MAX];
__device__ float g_a1f[N_MAX];       // atomic accum of sum dinv[src]
__device__ int   g_src[E_MAX];       // CSR src indices (weightless)

__device__ float g_a1[N_MAX];        // P·1
__device__ float g_at[N_MAX];        // dinv * a1
__device__ float g_a2[N_MAX];        // P²·1
__device__ float g_U[96 * 64];       // [W1@W3_top ; W2@W3_bot]
__device__ float g_c4[64];           // ([b1|b2]@W3)@W4
__device__ float g_e4[64];           // b3@W4
__device__ float g_f4[64];           // b4

__device__ __align__(16) __half g_T0[(size_t)N_MAX * 64];  // Dinv·(LC@U)
__device__ __align__(16) __half g_T1[(size_t)N_MAX * 64];  // Dinv²·(A+I)T0
__device__ __align__(16) __half g_T2[(size_t)N_MAX * 64];  // Dinv²·(A+I)T1
__device__ float                g_Y3[(size_t)N_MAX * 64];  // Dinv·(A+I)T2 = P³V

// ===== packed fp32x2 helpers (sm_103a) =====
__device__ __forceinline__ unsigned long long ffma2(unsigned long long a,
                                                    unsigned long long b,
                                                    unsigned long long c) {
    unsigned long long d;
    asm("fma.rn.f32x2 %0, %1, %2, %3;" : "=l"(d) : "l"(a), "l"(b), "l"(c));
    return d;
}
__device__ __forceinline__ unsigned long long pack2(float x) {
    unsigned long long d;
    asm("mov.b64 %0, {%1, %1};" : "=l"(d) : "r"(__float_as_uint(x)));
    return d;
}
__device__ __forceinline__ float2 unpack2(unsigned long long v) {
    unsigned int lo, hi;
    asm("mov.b64 {%0, %1}, %2;" : "=r"(lo), "=r"(hi) : "l"(v));
    return make_float2(__uint_as_float(lo), __uint_as_float(hi));
}

// ============================ graph construction ============================

__global__ void k_hist(const int* __restrict__ col, int E) {
    int e = blockIdx.x * blockDim.x + threadIdx.x;
    if (e < E) atomicAdd(&g_cnt[col[e]], 1);
}

__global__ void __launch_bounds__(1024) k_scan_local(int n) {
    __shared__ int s[1024];
    int tid = threadIdx.x;
    int i = blockIdx.x * 1024 + tid;
    int v = (i < n) ? g_cnt[i] : 0;
    s[tid] = v;
    __syncthreads();
    for (int d = 1; d < 1024; d <<= 1) {
        int t = (tid >= d) ? s[tid - d] : 0;
        __syncthreads();
        s[tid] += t;
        __syncthreads();
    }
    if (i < n) { g_off[i] = s[tid] - v; g_a1f[i] = 0.f; }
    if (tid == 1023) g_bsum[blockIdx.x] = s[1023];
}

__global__ void __launch_bounds__(1024) k_scan_bsum(int nb) {
    __shared__ int s[1024];
    int tid = threadIdx.x;
    int v = (tid < nb) ? g_bsum[tid] : 0;
    s[tid] = v;
    __syncthreads();
    for (int d = 1; d < 1024; d <<= 1) {
        int t = (tid >= d) ? s[tid - d] : 0;
        __syncthreads();
        s[tid] += t;
        __syncthreads();
    }
    if (tid < nb) g_bsum[tid] = s[tid] - v;
}

// weight precompute (independent of scan chain; 256 threads)
__global__ void k_wprep(const float* __restrict__ W1, const float* __restrict__ W2,
                        const float* __restrict__ W3, const float* __restrict__ W4,
                        const float* __restrict__ b1, const float* __restrict__ b2,
                        const float* __restrict__ b3, const float* __restrict__ b4) {
    __shared__ float sA[64 * 64], sB[64 * 64], sc3[64];
    int tid = threadIdx.x;

    for (int i = tid; i < 64 * 64; i += 256) { sA[i] = W1[i]; sB[i] = W3[i]; }
    __syncthreads();
    for (int o = tid; o < 64 * 64; o += 256) {
        int k = o >> 6, j = o & 63;
        float s = 0.f;
        for (int m = 0; m < 64; m++) s += sA[k * 64 + m] * sB[m * 64 + j];
        g_U[o] = s;
    }
    if (tid < 64) {
        float s = 0.f;
        for (int m = 0; m < 64; m++) s += b1[m] * sB[m * 64 + tid];
        sc3[tid] = s;
    }
    __syncthreads();

    for (int i = tid; i < 32 * 64; i += 256) sA[i] = W2[i];
    for (int i = tid; i < 64 * 64; i += 256) sB[i] = W3[64 * 64 + i];
    __syncthreads();
    for (int o = tid; o < 32 * 64; o += 256) {
        int k = o >> 6, j = o & 63;
        float s = 0.f;
        for (int m = 0; m < 64; m++) s += sA[k * 64 + m] * sB[m * 64 + j];
        g_U[64 * 64 + o] = s;
    }
    if (tid < 64) {
        float s = sc3[tid];
        for (int m = 0; m < 64; m++) s += b2[m] * sB[m * 64 + tid];
        sc3[tid] = s;
    }
    __syncthreads();

    for (int i = tid; i < 64 * 64; i += 256) sA[i] = W4[i];
    __syncthreads();
    if (tid < 64) {
        float s = 0.f, t = 0.f;
        for (int m = 0; m < 64; m++) {
            s += sc3[m] * sA[m * 64 + tid];
            t += b3[m]  * sA[m * 64 + tid];
        }
        g_c4[tid] = s; g_e4[tid] = t; g_f4[tid] = b4[tid];
    }
}

__global__ void k_scan_add(int n, int E) {
    int i = blockIdx.x * blockDim.x + threadIdx.x;
    if (i < n) {
        int o = g_off[i] + g_bsum[i >> 10];
        g_off[i]  = o;
        g_fill[i] = o;
        g_dinv[i] = rsqrtf((float)(g_cnt[i] + 1));
    }
    if (i == n) g_off[n] = E;
}

// fill CSR src; also accumulate a1f[c] += dinv[r]
__global__ void k_fill(const int* __restrict__ row, const int* __restrict__ col, int E) {
    int e = blockIdx.x * blockDim.x + threadIdx.x;
    if (e < E) {
        int r = row[e], c = col[e];
        int pos = atomicAdd(&g_fill[c], 1);
        g_src[pos] = r;
        atomicAdd(&g_a1f[c], g_dinv[r]);
    }
}

// ============================ gemm0: T0 = Dinv·([L|C]@U), finalize a1 ============================

__global__ void __launch_bounds__(256) k_gemm0(const float* __restrict__ latent,
                                               const float* __restrict__ cond, int n) {
    __shared__ __align__(16) float sW[96 * 64];
    for (int i = threadIdx.x; i < 96 * 64; i += blockDim.x) sW[i] = g_U[i];
    __syncthreads();
    int node = blockIdx.x * blockDim.x + threadIdx.x;
    if (node >= n) return;

    unsigned long long acc[32];
#pragma unroll
    for (int j = 0; j < 32; j++) acc[j] = 0ull;

    const float* pL = latent + (size_t)node * 64;
    const float* pC = cond   + (size_t)node * 32;
#pragma unroll 2
    for (int k = 0; k < 96; k += 4) {
        float4 av = (k < 64) ? *reinterpret_cast<const float4*>(pL + k)
                             : *reinterpret_cast<const float4*>(pC + (k - 64));
        unsigned long long p0 = pack2(av.x), p1 = pack2(av.y);
        unsigned long long p2 = pack2(av.z), p3 = pack2(av.w);
        const ulonglong2* w0 = reinterpret_cast<const ulonglong2*>(sW + (k + 0) * 64);
        const ulonglong2* w1 = reinterpret_cast<const ulonglong2*>(sW + (k + 1) * 64);
        const ulonglong2* w2 = reinterpret_cast<const ulonglong2*>(sW + (k + 2) * 64);
        const ulonglong2* w3 = reinterpret_cast<const ulonglong2*>(sW + (k + 3) * 64);
#pragma unroll
        for (int j = 0; j < 16; j++) {
            ulonglong2 q;
            q = w0[j]; acc[2*j] = ffma2(p0, q.x, acc[2*j]); acc[2*j+1] = ffma2(p0, q.y, acc[2*j+1]);
            q = w1[j]; acc[2*j] = ffma2(p1, q.x, acc[2*j]); acc[2*j+1] = ffma2(p1, q.y, acc[2*j+1]);
            q = w2[j]; acc[2*j] = ffma2(p2, q.x, acc[2*j]); acc[2*j+1] = ffma2(p2, q.y, acc[2*j+1]);
            q = w3[j]; acc[2*j] = ffma2(p3, q.x, acc[2*j]); acc[2*j+1] = ffma2(p3, q.y, acc[2*j+1]);
        }
    }

    float dn = g_dinv[node];
    float a1 = dn * (g_a1f[node] + dn);
    g_a1[node] = a1;
    g_at[node] = dn * a1;

    __half* yp = g_T0 + (size_t)node * 64;
#pragma unroll
    for (int j = 0; j < 8; j++) {
        float2 f0 = unpack2(acc[4*j+0]);
        float2 f1 = unpack2(acc[4*j+1]);
        float2 f2 = unpack2(acc[4*j+2]);
        float2 f3 = unpack2(acc[4*j+3]);
        __half2 h0 = __floats2half2_rn(f0.x * dn, f0.y * dn);
        __half2 h1 = __floats2half2_rn(f1.x * dn, f1.y * dn);
        __half2 h2 = __floats2half2_rn(f2.x * dn, f2.y * dn);
        __half2 h3 = __floats2half2_rn(f3.x * dn, f3.y * dn);
        uint4 u = make_uint4(*reinterpret_cast<unsigned*>(&h0), *reinterpret_cast<unsigned*>(&h1),
                             *reinterpret_cast<unsigned*>(&h2), *reinterpret_cast<unsigned*>(&h3));
        *reinterpret_cast<uint4*>(yp + 8 * j) = u;
    }
}

// a2 = P·a1 = dinv[c]·( sum at[src] + at[c] )
__global__ void k_a2(int n) {
    int wid  = (blockIdx.x * blockDim.x + threadIdx.x) >> 5;
    int lane = threadIdx.x & 31;
    if (wid >= n) return;
    int beg = g_off[wid], end = g_off[wid + 1];
    float acc = 0.f;
    for (int e = beg + lane; e < end; e += 32) acc += g_at[g_src[e]];
    for (int d = 16; d; d >>= 1) acc += __shfl_down_sync(0xffffffffu, acc, d);
    if (lane == 0) g_a2[wid] = g_dinv[wid] * (acc + g_at[wid]);
}

// ============================ weightless aggregation ============================
// G[c] = sum_{e->c} X[src_e] + X[c];  MODE 0: Y = dinv²·G (fp16), MODE 1: Y = dinv·G (fp32)

template <int MODE>
__global__ void __launch_bounds__(256) k_aggp(const __half* __restrict__ X,
                                              void* __restrict__ Yv, int n) {
    int wid  = (blockIdx.x * blockDim.x + threadIdx.x) >> 5;
    int lane = threadIdx.x & 31;
    if (wid >= n) return;

    const int f0 = lane * 2;
    int e = g_off[wid];
    const int end = g_off[wid + 1];
    float a0 = 0.f, a1v = 0.f;

#define GATH(SRC) { __half2 h = *reinterpret_cast<const __half2*>(X + (size_t)(SRC) * 64 + f0); \
                    float2 f = __half22float2(h); a0 += f.x; a1v += f.y; }

    for (; e + 8 <= end; e += 8) {
        int s0 = g_src[e+0], s1 = g_src[e+1], s2 = g_src[e+2], s3 = g_src[e+3];
        int s4 = g_src[e+4], s5 = g_src[e+5], s6 = g_src[e+6], s7 = g_src[e+7];
        GATH(s0) GATH(s1) GATH(s2) GATH(s3) GATH(s4) GATH(s5) GATH(s6) GATH(s7)
    }
    for (; e < end; ++e) { int s = g_src[e]; GATH(s) }
    GATH(wid)  // self loop
#undef GATH

    float dn = g_dinv[wid];
    if (MODE == 0) {
        float s = dn * dn;
        __half2 h = __floats2half2_rn(a0 * s, a1v * s);
        *reinterpret_cast<__half2*>((__half*)Yv + (size_t)wid * 64 + f0) = h;
    } else {
        *reinterpret_cast<float2*>((float*)Yv + (size_t)wid * 64 + f0) =
            make_float2(a0 * dn, a1v * dn);
    }
}

// ============================ final GEMM ============================
// out = Y3@W4 + a2·c4 + a1·e4 + f4
__global__ void __launch_bounds__(256) k_gemm_final(const float* __restrict__ A,
                                                    const float* __restrict__ Wg,
                                                    float* __restrict__ Y, int n) {
    __shared__ __align__(16) float sW[64 * 64];
    __shared__ float sc[64], se[64], sf[64];
    for (int i = threadIdx.x; i < 64 * 64; i += blockDim.x) sW[i] = Wg[i];
    if (threadIdx.x < 64) {
        sc[threadIdx.x] = g_c4[threadIdx.x];
        se[threadIdx.x] = g_e4[threadIdx.x];
        sf[threadIdx.x] = g_f4[threadIdx.x];
    }
    __syncthreads();
    int node = blockIdx.x * blockDim.x + threadIdx.x;
    if (node >= n) return;

    unsigned long long acc[32];
#pragma unroll
    for (int j = 0; j < 32; j++) acc[j] = 0ull;

    const float* arow = A + (size_t)node * 64;
#pragma unroll 2
    for (int k = 0; k < 64; k += 4) {
        float4 av = *reinterpret_cast<const float4*>(arow + k);
        unsigned long long p0 = pack2(av.x), p1 = pack2(av.y);
        unsigned long long p2 = pack2(av.z), p3 = pack2(av.w);
        const ulonglong2* w0 = reinterpret_cast<const ulonglong2*>(sW + (k + 0) * 64);
        const ulonglong2* w1 = reinterpret_cast<const ulonglong2*>(sW + (k + 1) * 64);
        const ulonglong2* w2 = reinterpret_cast<const ulonglong2*>(sW + (k + 2) * 64);
        const ulonglong2* w3 = reinterpret_cast<const ulonglong2*>(sW + (k + 3) * 64);
#pragma unroll
        for (int j = 0; j < 16; j++) {
            ulonglong2 q;
            q = w0[j]; acc[2*j] = ffma2(p0, q.x, acc[2*j]); acc[2*j+1] = ffma2(p0, q.y, acc[2*j+1]);
            q = w1[j]; acc[2*j] = ffma2(p1, q.x, acc[2*j]); acc[2*j+1] = ffma2(p1, q.y, acc[2*j+1]);
            q = w2[j]; acc[2*j] = ffma2(p2, q.x, acc[2*j]); acc[2*j+1] = ffma2(p2, q.y, acc[2*j+1]);
            q = w3[j]; acc[2*j] = ffma2(p3, q.x, acc[2*j]); acc[2*j+1] = ffma2(p3, q.y, acc[2*j+1]);
        }
    }

    float av1 = g_a1[node], av2 = g_a2[node];
    float* yrow = Y + (size_t)node * 64;
#pragma unroll
    for (int j = 0; j < 16; j++) {
        float2 lo = unpack2(acc[2*j]);
        float2 hi = unpack2(acc[2*j+1]);
        int c0 = 4 * j;
        float4 o;
        o.x = lo.x + av2 * sc[c0+0] + av1 * se[c0+0] + sf[c0+0];
        o.y = lo.y + av2 * sc[c0+1] + av1 * se[c0+1] + sf[c0+1];
        o.z = hi.x + av2 * sc[c0+2] + av1 * se[c0+2] + sf[c0+2];
        o.w = hi.y + av2 * sc[c0+3] + av1 * se[c0+3] + sf[c0+3];
        *reinterpret_cast<float4*>(yrow + c0) = o;
    }
}

// ============================ launch ============================

extern "C" void kernel_launch(void* const* d_in, const int* in_sizes, int n_in,
                              void* d_out, int out_size) {
    const float* latent = (const float*)d_in[0];
    const float* cond   = (const float*)d_in[1];
    const int*   edge   = (const int*)  d_in[2];
    const float* W1 = (const float*)d_in[3];
    const float* b1 = (const float*)d_in[4];
    const float* W2 = (const float*)d_in[5];
    const float* b2 = (const float*)d_in[6];
    const float* W3 = (const float*)d_in[7];
    const float* b3 = (const float*)d_in[8];
    const float* W4 = (const float*)d_in[9];
    const float* b4 = (const float*)d_in[10];

    const int n = in_sizes[0] / 64;      // 100000
    const int E = in_sizes[2] / 2;       // 1600000
    const int* row = edge;
    const int* col = edge + E;

    static int* pCnt = nullptr;
    static __half *pT0 = nullptr, *pT1 = nullptr, *pT2 = nullptr;
    static float *pY3 = nullptr;
    if (!pCnt) {
        cudaGetSymbolAddress((void**)&pCnt, g_cnt);
        cudaGetSymbolAddress((void**)&pT0,  g_T0);
        cudaGetSymbolAddress((void**)&pT1,  g_T1);
        cudaGetSymbolAddress((void**)&pT2,  g_T2);
        cudaGetSymbolAddress((void**)&pY3,  g_Y3);
    }

    const int TB  = 256;
    const int gN  = (n + TB - 1) / TB;
    const int gE  = (E + TB - 1) / TB;
    const int nbS = (n + 1023) / 1024;
    const int gN1 = (n + 1 + TB - 1) / TB;
    const int gW  = (n + 7) / 8;   // 8 warps/block

    // ---- graph structure ----
    cudaMemsetAsync(pCnt, 0, (size_t)n * sizeof(int));
    k_hist<<<gE, TB>>>(col, E);
    k_scan_local<<<nbS, 1024>>>(n);
    k_scan_bsum<<<1, 1024>>>(nbS);
    k_wprep<<<1, 256>>>(W1, W2, W3, W4, b1, b2, b3, b4);   // independent of scan
    k_scan_add<<<gN1, TB>>>(n, E);
    k_fill<<<gE, TB>>>(row, col, E);

    // ---- V = [L|C]@U, scaled by dinv; finalize a1 ----
    k_gemm0<<<gN, TB>>>(latent, cond, n);
    // ---- a2 = P·a1 ----
    k_a2<<<gW, TB>>>(n);
    // ---- three weightless aggregation passes ----
    k_aggp<0><<<gW, TB>>>(pT0, pT1, n);
    k_aggp<0><<<gW, TB>>>(pT1, pT2, n);
    k_aggp<1><<<gW, TB>>>(pT2, pY3, n);
    // ---- out = Y3@W4 + a2·c4 + a1·e4 + f4 ----
    k_gemm_final<<<gN, TB>>>(pY3, W4, (float*)d_out, n);
}

// round 7
// speedup vs baseline: 1.5901x; 1.0775x over previous
#include <cuda_runtime.h>
#include <cuda_fp16.h>

// ===== static scratch (allocation-free rule: __device__ globals) =====
#define N_MAX 100352
#define E_MAX 1700032

__device__ int   g_cnt[N_MAX];
__device__ int   g_fill[N_MAX];
__device__ int   g_off[N_MAX + 1];
__device__ int   g_bsum[1024];
__device__ float g_dinv[N_MAX];
__device__ float g_a1f[N_MAX];       // atomic accum of sum dinv[src]
__device__ int   g_src[E_MAX];       // CSR src indices (weightless)

__device__ float g_a1[N_MAX];        // P·1
__device__ float g_at[N_MAX];        // dinv * a1
__device__ float g_a2[N_MAX];        // P²·1
__device__ float g_U[96 * 64];       // [W1@W3_top ; W2@W3_bot]
__device__ float g_c4[64];           // ([b1|b2]@W3)@W4
__device__ float g_e4[64];           // b3@W4
__device__ float g_f4[64];           // b4

__device__ __align__(16) __half g_T0[(size_t)N_MAX * 64];  // Dinv·(LC@U)
__device__ __align__(16) __half g_T1[(size_t)N_MAX * 64];  // Dinv²·(A+I)T0
__device__ __align__(16) __half g_T2[(size_t)N_MAX * 64];  // Dinv²·(A+I)T1
__device__ float                g_Y3[(size_t)N_MAX * 64];  // Dinv·(A+I)T2 = P³V

// ===== packed fp32x2 helpers (sm_103a) =====
__device__ __forceinline__ unsigned long long ffma2(unsigned long long a,
                                                    unsigned long long b,
                                                    unsigned long long c) {
    unsigned long long d;
    asm("fma.rn.f32x2 %0, %1, %2, %3;" : "=l"(d) : "l"(a), "l"(b), "l"(c));
    return d;
}
__device__ __forceinline__ unsigned long long pack2(float x) {
    unsigned long long d;
    asm("mov.b64 %0, {%1, %1};" : "=l"(d) : "r"(__float_as_uint(x)));
    return d;
}
__device__ __forceinline__ float2 unpack2(unsigned long long v) {
    unsigned int lo, hi;
    asm("mov.b64 {%0, %1}, %2;" : "=r"(lo), "=r"(hi) : "l"(v));
    return make_float2(__uint_as_float(lo), __uint_as_float(hi));
}

// ============================ graph construction ============================

__global__ void k_hist(const int* __restrict__ col, int E) {
    int e = blockIdx.x * blockDim.x + threadIdx.x;
    if (e < E) atomicAdd(&g_cnt[col[e]], 1);
}

__global__ void __launch_bounds__(1024) k_scan_local(int n) {
    __shared__ int s[1024];
    int tid = threadIdx.x;
    int i = blockIdx.x * 1024 + tid;
    int v = (i < n) ? g_cnt[i] : 0;
    s[tid] = v;
    __syncthreads();
    for (int d = 1; d < 1024; d <<= 1) {
        int t = (tid >= d) ? s[tid - d] : 0;
        __syncthreads();
        s[tid] += t;
        __syncthreads();
    }
    if (i < n) { g_off[i] = s[tid] - v; g_a1f[i] = 0.f; }
    if (tid == 1023) g_bsum[blockIdx.x] = s[1023];
}

__global__ void __launch_bounds__(1024) k_scan_bsum(int nb) {
    __shared__ int s[1024];
    int tid = threadIdx.x;
    int v = (tid < nb) ? g_bsum[tid] : 0;
    s[tid] = v;
    __syncthreads();
    for (int d = 1; d < 1024; d <<= 1) {
        int t = (tid >= d) ? s[tid - d] : 0;
        __syncthreads();
        s[tid] += t;
        __syncthreads();
    }
    if (tid < nb) g_bsum[tid] = s[tid] - v;
}

// ============================ weight precompute (parallel) ============================
// blocks 0..23: 4x64 tile of U = [W1;W2] @ W3 (block b covers U rows b*4..b*4+3)
// block 24:     bias vectors c4 = ([b1|b2]@W3)@W4, e4 = b3@W4, f4 = b4
__global__ void __launch_bounds__(256) k_wprep2(
        const float* __restrict__ W1, const float* __restrict__ W2,
        const float* __restrict__ W3, const float* __restrict__ W4,
        const float* __restrict__ b1, const float* __restrict__ b2,
        const float* __restrict__ b3, const float* __restrict__ b4) {
    int tid = threadIdx.x;
    int b = blockIdx.x;
    if (b < 24) {
        __shared__ float sB[64 * 64];   // relevant half of W3
        __shared__ float sA[4 * 64];    // 4 rows of [W1;W2]
        int k0 = b * 4;
        int half = (k0 >= 64);
        const float* Wsrc = W3 + (size_t)half * 64 * 64;
        for (int i = tid; i < 64 * 64; i += 256) sB[i] = Wsrc[i];
        const float* Arow = half ? (W2 + (size_t)(k0 - 64) * 64) : (W1 + (size_t)k0 * 64);
        if (tid < 256) { /* 4*64 = 256 */ sA[tid] = Arow[tid]; }
        __syncthreads();
        int k = tid >> 6, j = tid & 63;
        float s = 0.f;
#pragma unroll
        for (int m = 0; m < 64; m++) s += sA[k * 64 + m] * sB[m * 64 + j];
        g_U[(k0 + k) * 64 + j] = s;
    } else {
        __shared__ float c3[64];
        int j = tid & 63;
        if (tid < 64) {
            float s = 0.f;
            for (int m = 0; m < 128; m++)
                s += ((m < 64) ? b1[m] : b2[m - 64]) * W3[m * 64 + j];
            c3[j] = s;
        }
        __syncthreads();
        if (tid < 64) {
            float s = 0.f, t = 0.f;
            for (int m = 0; m < 64; m++) {
                s += c3[m] * W4[m * 64 + j];
                t += b3[m] * W4[m * 64 + j];
            }
            g_c4[j] = s; g_e4[j] = t; g_f4[j] = b4[j];
        }
    }
}

__global__ void k_scan_add(int n, int E) {
    int i = blockIdx.x * blockDim.x + threadIdx.x;
    if (i < n) {
        int o = g_off[i] + g_bsum[i >> 10];
        g_off[i]  = o;
        g_fill[i] = o;
        g_dinv[i] = rsqrtf((float)(g_cnt[i] + 1));
    }
    if (i == n) g_off[n] = E;
}

// fill CSR src; also accumulate a1f[c] += dinv[r]
__global__ void k_fill(const int* __restrict__ row, const int* __restrict__ col, int E) {
    int e = blockIdx.x * blockDim.x + threadIdx.x;
    if (e < E) {
        int r = row[e], c = col[e];
        int pos = atomicAdd(&g_fill[c], 1);
        g_src[pos] = r;
        atomicAdd(&g_a1f[c], g_dinv[r]);
    }
}

// ============================ gemm0: T0 = Dinv·([L|C]@U), finalize a1 ============================

__global__ void __launch_bounds__(256) k_gemm0(const float* __restrict__ latent,
                                               const float* __restrict__ cond, int n) {
    __shared__ __align__(16) float sW[96 * 64];
    for (int i = threadIdx.x; i < 96 * 64; i += blockDim.x) sW[i] = g_U[i];
    __syncthreads();
    int node = blockIdx.x * blockDim.x + threadIdx.x;
    if (node >= n) return;

    unsigned long long acc[32];
#pragma unroll
    for (int j = 0; j < 32; j++) acc[j] = 0ull;

    const float* pL = latent + (size_t)node * 64;
    const float* pC = cond   + (size_t)node * 32;
#pragma unroll 2
    for (int k = 0; k < 96; k += 4) {
        float4 av = (k < 64) ? *reinterpret_cast<const float4*>(pL + k)
                             : *reinterpret_cast<const float4*>(pC + (k - 64));
        unsigned long long p0 = pack2(av.x), p1 = pack2(av.y);
        unsigned long long p2 = pack2(av.z), p3 = pack2(av.w);
        const ulonglong2* w0 = reinterpret_cast<const ulonglong2*>(sW + (k + 0) * 64);
        const ulonglong2* w1 = reinterpret_cast<const ulonglong2*>(sW + (k + 1) * 64);
        const ulonglong2* w2 = reinterpret_cast<const ulonglong2*>(sW + (k + 2) * 64);
        const ulonglong2* w3 = reinterpret_cast<const ulonglong2*>(sW + (k + 3) * 64);
#pragma unroll
        for (int j = 0; j < 16; j++) {
            ulonglong2 q;
            q = w0[j]; acc[2*j] = ffma2(p0, q.x, acc[2*j]); acc[2*j+1] = ffma2(p0, q.y, acc[2*j+1]);
            q = w1[j]; acc[2*j] = ffma2(p1, q.x, acc[2*j]); acc[2*j+1] = ffma2(p1, q.y, acc[2*j+1]);
            q = w2[j]; acc[2*j] = ffma2(p2, q.x, acc[2*j]); acc[2*j+1] = ffma2(p2, q.y, acc[2*j+1]);
            q = w3[j]; acc[2*j] = ffma2(p3, q.x, acc[2*j]); acc[2*j+1] = ffma2(p3, q.y, acc[2*j+1]);
        }
    }

    float dn = g_dinv[node];
    float a1 = dn * (g_a1f[node] + dn);
    g_a1[node] = a1;
    g_at[node] = dn * a1;

    __half* yp = g_T0 + (size_t)node * 64;
#pragma unroll
    for (int j = 0; j < 8; j++) {
        float2 f0 = unpack2(acc[4*j+0]);
        float2 f1 = unpack2(acc[4*j+1]);
        float2 f2 = unpack2(acc[4*j+2]);
        float2 f3 = unpack2(acc[4*j+3]);
        __half2 h0 = __floats2half2_rn(f0.x * dn, f0.y * dn);
        __half2 h1 = __floats2half2_rn(f1.x * dn, f1.y * dn);
        __half2 h2 = __floats2half2_rn(f2.x * dn, f2.y * dn);
        __half2 h3 = __floats2half2_rn(f3.x * dn, f3.y * dn);
        uint4 u = make_uint4(*reinterpret_cast<unsigned*>(&h0), *reinterpret_cast<unsigned*>(&h1),
                             *reinterpret_cast<unsigned*>(&h2), *reinterpret_cast<unsigned*>(&h3));
        *reinterpret_cast<uint4*>(yp + 8 * j) = u;
    }
}

// a2 = P·a1 = dinv[c]·( sum at[src] + at[c] )
__global__ void k_a2(int n) {
    int wid  = (blockIdx.x * blockDim.x + threadIdx.x) >> 5;
    int lane = threadIdx.x & 31;
    if (wid >= n) return;
    int beg = g_off[wid], end = g_off[wid + 1];
    float acc = 0.f;
    for (int e = beg + lane; e < end; e += 32) acc += g_at[g_src[e]];
    for (int d = 16; d; d >>= 1) acc += __shfl_down_sync(0xffffffffu, acc, d);
    if (lane == 0) g_a2[wid] = g_dinv[wid] * (acc + g_at[wid]);
}

// ============================ weightless aggregation ============================
// G[c] = sum_{e->c} X[src_e] + X[c];  MODE 0: Y = dinv²·G (fp16), MODE 1: Y = dinv·G (fp32)

template <int MODE>
__global__ void __launch_bounds__(256) k_aggp(const __half* __restrict__ X,
                                              void* __restrict__ Yv, int n) {
    int wid  = (blockIdx.x * blockDim.x + threadIdx.x) >> 5;
    int lane = threadIdx.x & 31;
    if (wid >= n) return;

    const int f0 = lane * 2;
    int e = g_off[wid];
    const int end = g_off[wid + 1];
    float a0 = 0.f, a1v = 0.f;

#define GATH(SRC) { __half2 h = *reinterpret_cast<const __half2*>(X + (size_t)(SRC) * 64 + f0); \
                    float2 f = __half22float2(h); a0 += f.x; a1v += f.y; }

    for (; e + 8 <= end; e += 8) {
        int s0 = g_src[e+0], s1 = g_src[e+1], s2 = g_src[e+2], s3 = g_src[e+3];
        int s4 = g_src[e+4], s5 = g_src[e+5], s6 = g_src[e+6], s7 = g_src[e+7];
        GATH(s0) GATH(s1) GATH(s2) GATH(s3) GATH(s4) GATH(s5) GATH(s6) GATH(s7)
    }
    for (; e < end; ++e) { int s = g_src[e]; GATH(s) }
    GATH(wid)  // self loop
#undef GATH

    float dn = g_dinv[wid];
    if (MODE == 0) {
        float s = dn * dn;
        __half2 h = __floats2half2_rn(a0 * s, a1v * s);
        *reinterpret_cast<__half2*>((__half*)Yv + (size_t)wid * 64 + f0) = h;
    } else {
        *reinterpret_cast<float2*>((float*)Yv + (size_t)wid * 64 + f0) =
            make_float2(a0 * dn, a1v * dn);
    }
}

// ============================ final GEMM ============================
// out = Y3@W4 + a2·c4 + a1·e4 + f4
__global__ void __launch_bounds__(256) k_gemm_final(const float* __restrict__ A,
                                                    const float* __restrict__ Wg,
                                                    float* __restrict__ Y, int n) {
    __shared__ __align__(16) float sW[64 * 64];
    __shared__ float sc[64], se[64], sf[64];
    for (int i = threadIdx.x; i < 64 * 64; i += blockDim.x) sW[i] = Wg[i];
    if (threadIdx.x < 64) {
        sc[threadIdx.x] = g_c4[threadIdx.x];
        se[threadIdx.x] = g_e4[threadIdx.x];
        sf[threadIdx.x] = g_f4[threadIdx.x];
    }
    __syncthreads();
    int node = blockIdx.x * blockDim.x + threadIdx.x;
    if (node >= n) return;

    unsigned long long acc[32];
#pragma unroll
    for (int j = 0; j < 32; j++) acc[j] = 0ull;

    const float* arow = A + (size_t)node * 64;
#pragma unroll 2
    for (int k = 0; k < 64; k += 4) {
        float4 av = *reinterpret_cast<const float4*>(arow + k);
        unsigned long long p0 = pack2(av.x), p1 = pack2(av.y);
        unsigned long long p2 = pack2(av.z), p3 = pack2(av.w);
        const ulonglong2* w0 = reinterpret_cast<const ulonglong2*>(sW + (k + 0) * 64);
        const ulonglong2* w1 = reinterpret_cast<const ulonglong2*>(sW + (k + 1) * 64);
        const ulonglong2* w2 = reinterpret_cast<const ulonglong2*>(sW + (k + 2) * 64);
        const ulonglong2* w3 = reinterpret_cast<const ulonglong2*>(sW + (k + 3) * 64);
#pragma unroll
        for (int j = 0; j < 16; j++) {
            ulonglong2 q;
            q = w0[j]; acc[2*j] = ffma2(p0, q.x, acc[2*j]); acc[2*j+1] = ffma2(p0, q.y, acc[2*j+1]);
            q = w1[j]; acc[2*j] = ffma2(p1, q.x, acc[2*j]); acc[2*j+1] = ffma2(p1, q.y, acc[2*j+1]);
            q = w2[j]; acc[2*j] = ffma2(p2, q.x, acc[2*j]); acc[2*j+1] = ffma2(p2, q.y, acc[2*j+1]);
            q = w3[j]; acc[2*j] = ffma2(p3, q.x, acc[2*j]); acc[2*j+1] = ffma2(p3, q.y, acc[2*j+1]);
        }
    }

    float av1 = g_a1[node], av2 = g_a2[node];
    float* yrow = Y + (size_t)node * 64;
#pragma unroll
    for (int j = 0; j < 16; j++) {
        float2 lo = unpack2(acc[2*j]);
        float2 hi = unpack2(acc[2*j+1]);
        int c0 = 4 * j;
        float4 o;
        o.x = lo.x + av2 * sc[c0+0] + av1 * se[c0+0] + sf[c0+0];
        o.y = lo.y + av2 * sc[c0+1] + av1 * se[c0+1] + sf[c0+1];
        o.z = hi.x + av2 * sc[c0+2] + av1 * se[c0+2] + sf[c0+2];
        o.w = hi.y + av2 * sc[c0+3] + av1 * se[c0+3] + sf[c0+3];
        *reinterpret_cast<float4*>(yrow + c0) = o;
    }
}

// ============================ launch ============================

extern "C" void kernel_launch(void* const* d_in, const int* in_sizes, int n_in,
                              void* d_out, int out_size) {
    const float* latent = (const float*)d_in[0];
    const float* cond   = (const float*)d_in[1];
    const int*   edge   = (const int*)  d_in[2];
    const float* W1 = (const float*)d_in[3];
    const float* b1 = (const float*)d_in[4];
    const float* W2 = (const float*)d_in[5];
    const float* b2 = (const float*)d_in[6];
    const float* W3 = (const float*)d_in[7];
    const float* b3 = (const float*)d_in[8];
    const float* W4 = (const float*)d_in[9];
    const float* b4 = (const float*)d_in[10];

    const int n = in_sizes[0] / 64;      // 100000
    const int E = in_sizes[2] / 2;       // 1600000
    const int* row = edge;
    const int* col = edge + E;

    static int* pCnt = nullptr;
    static __half *pT0 = nullptr, *pT1 = nullptr, *pT2 = nullptr;
    static float *pY3 = nullptr;
    if (!pCnt) {
        cudaGetSymbolAddress((void**)&pCnt, g_cnt);
        cudaGetSymbolAddress((void**)&pT0,  g_T0);
        cudaGetSymbolAddress((void**)&pT1,  g_T1);
        cudaGetSymbolAddress((void**)&pT2,  g_T2);
        cudaGetSymbolAddress((void**)&pY3,  g_Y3);
    }

    const int TB  = 256;
    const int gN  = (n + TB - 1) / TB;
    const int gE  = (E + TB - 1) / TB;
    const int nbS = (n + 1023) / 1024;
    const int gN1 = (n + 1 + TB - 1) / TB;
    const int gW  = (n + 7) / 8;   // 8 warps/block

    // ---- graph structure ----
    cudaMemsetAsync(pCnt, 0, (size_t)n * sizeof(int));
    k_hist<<<gE, TB>>>(col, E);
    k_scan_local<<<nbS, 1024>>>(n);
    k_scan_bsum<<<1, 1024>>>(nbS);
    k_wprep2<<<25, 256>>>(W1, W2, W3, W4, b1, b2, b3, b4);
    k_scan_add<<<gN1, TB>>>(n, E);
    k_fill<<<gE, TB>>>(row, col, E);

    // ---- V = [L|C]@U, scaled by dinv; finalize a1 ----
    k_gemm0<<<gN, TB>>>(latent, cond, n);
    // ---- a2 = P·a1 ----
    k_a2<<<gW, TB>>>(n);
    // ---- three weightless aggregation passes ----
    k_aggp<0><<<gW, TB>>>(pT0, pT1, n);
    k_aggp<0><<<gW, TB>>>(pT1, pT2, n);
    k_aggp<1><<<gW, TB>>>(pT2, pY3, n);
    // ---- out = Y3@W4 + a2·c4 + a1·e4 + f4 ----
    k_gemm_final<<<gN, TB>>>(pY3, W4, (float*)d_out, n);
}

// round 8
// speedup vs baseline: 1.7821x; 1.1207x over previous
#include <cuda_runtime.h>
#include <cuda_fp16.h>

// ===== static scratch (allocation-free rule: __device__ globals) =====
#define N_MAX 100352
#define E_MAX 1700032

__device__ int   g_cnt[N_MAX];
__device__ int   g_fill[N_MAX];
__device__ int   g_off[N_MAX + 1];
__device__ int   g_bsum[1024];
__device__ float g_dinv[N_MAX];
__device__ float g_a1f[N_MAX];       // atomic accum of sum dinv[src]
__device__ int   g_src[E_MAX];       // CSR src indices (weightless)

__device__ float g_a1[N_MAX];        // P·1
__device__ float g_at[N_MAX];        // dinv * a1
__device__ float g_a2[N_MAX];        // P²·1
__device__ float g_U[96 * 64];       // [W1@W3_top ; W2@W3_bot]
__device__ float g_c4[64];           // ([b1|b2]@W3)@W4
__device__ float g_e4[64];           // b3@W4
__device__ float g_f4[64];           // b4

__device__ __align__(16) __half g_T0[(size_t)N_MAX * 64];  // V, then Dinv·V (in place)
__device__ __align__(16) __half g_T1[(size_t)N_MAX * 64];  // Dinv²·(A+I)T0
__device__ __align__(16) __half g_T2[(size_t)N_MAX * 64];  // Dinv²·(A+I)T1
__device__ float                g_Y3[(size_t)N_MAX * 64];  // Dinv·(A+I)T2 = P³V

// ===== packed fp32x2 helpers (sm_103a) =====
__device__ __forceinline__ unsigned long long ffma2(unsigned long long a,
                                                    unsigned long long b,
                                                    unsigned long long c) {
    unsigned long long d;
    asm("fma.rn.f32x2 %0, %1, %2, %3;" : "=l"(d) : "l"(a), "l"(b), "l"(c));
    return d;
}
__device__ __forceinline__ unsigned long long pack2(float x) {
    unsigned long long d;
    asm("mov.b64 %0, {%1, %1};" : "=l"(d) : "r"(__float_as_uint(x)));
    return d;
}
__device__ __forceinline__ float2 unpack2(unsigned long long v) {
    unsigned int lo, hi;
    asm("mov.b64 {%0, %1}, %2;" : "=r"(lo), "=r"(hi) : "l"(v));
    return make_float2(__uint_as_float(lo), __uint_as_float(hi));
}

// ============================ graph construction ============================

__global__ void k_hist(const int* __restrict__ col, int E) {
    int e = blockIdx.x * blockDim.x + threadIdx.x;
    if (e < E) atomicAdd(&g_cnt[col[e]], 1);
}

__global__ void __launch_bounds__(1024) k_scan_local(int n) {
    __shared__ int s[1024];
    int tid = threadIdx.x;
    int i = blockIdx.x * 1024 + tid;
    int v = (i < n) ? g_cnt[i] : 0;
    s[tid] = v;
    __syncthreads();
    for (int d = 1; d < 1024; d <<= 1) {
        int t = (tid >= d) ? s[tid - d] : 0;
        __syncthreads();
        s[tid] += t;
        __syncthreads();
    }
    if (i < n) { g_off[i] = s[tid] - v; g_a1f[i] = 0.f; }
    if (tid == 1023) g_bsum[blockIdx.x] = s[1023];
}

__global__ void __launch_bounds__(1024) k_scan_bsum(int nb) {
    __shared__ int s[1024];
    int tid = threadIdx.x;
    int v = (tid < nb) ? g_bsum[tid] : 0;
    s[tid] = v;
    __syncthreads();
    for (int d = 1; d < 1024; d <<= 1) {
        int t = (tid >= d) ? s[tid - d] : 0;
        __syncthreads();
        s[tid] += t;
        __syncthreads();
    }
    if (tid < nb) g_bsum[tid] = s[tid] - v;
}

// ============================ weight precompute (parallel) ============================
__global__ void __launch_bounds__(256) k_wprep2(
        const float* __restrict__ W1, const float* __restrict__ W2,
        const float* __restrict__ W3, const float* __restrict__ W4,
        const float* __restrict__ b1, const float* __restrict__ b2,
        const float* __restrict__ b3, const float* __restrict__ b4) {
    int tid = threadIdx.x;
    int b = blockIdx.x;
    if (b < 24) {
        __shared__ float sB[64 * 64];
        __shared__ float sA[4 * 64];
        int k0 = b * 4;
        int half = (k0 >= 64);
        const float* Wsrc = W3 + (size_t)half * 64 * 64;
        for (int i = tid; i < 64 * 64; i += 256) sB[i] = Wsrc[i];
        const float* Arow = half ? (W2 + (size_t)(k0 - 64) * 64) : (W1 + (size_t)k0 * 64);
        sA[tid] = Arow[tid];
        __syncthreads();
        int k = tid >> 6, j = tid & 63;
        float s = 0.f;
#pragma unroll
        for (int m = 0; m < 64; m++) s += sA[k * 64 + m] * sB[m * 64 + j];
        g_U[(k0 + k) * 64 + j] = s;
    } else {
        __shared__ float c3[64];
        int j = tid & 63;
        if (tid < 64) {
            float s = 0.f;
            for (int m = 0; m < 128; m++)
                s += ((m < 64) ? b1[m] : b2[m - 64]) * W3[m * 64 + j];
            c3[j] = s;
        }
        __syncthreads();
        if (tid < 64) {
            float s = 0.f, t = 0.f;
            for (int m = 0; m < 64; m++) {
                s += c3[m] * W4[m * 64 + j];
                t += b3[m] * W4[m * 64 + j];
            }
            g_c4[j] = s; g_e4[j] = t; g_f4[j] = b4[j];
        }
    }
}

__global__ void k_scan_add(int n, int E) {
    int i = blockIdx.x * blockDim.x + threadIdx.x;
    if (i < n) {
        int o = g_off[i] + g_bsum[i >> 10];
        g_off[i]  = o;
        g_fill[i] = o;
        g_dinv[i] = rsqrtf((float)(g_cnt[i] + 1));
    }
    if (i == n) g_off[n] = E;
}

// fill CSR src; also accumulate a1f[c] += dinv[r]
__global__ void k_fill(const int* __restrict__ row, const int* __restrict__ col, int E) {
    int e = blockIdx.x * blockDim.x + threadIdx.x;
    if (e < E) {
        int r = row[e], c = col[e];
        int pos = atomicAdd(&g_fill[c], 1);
        g_src[pos] = r;
        atomicAdd(&g_a1f[c], g_dinv[r]);
    }
}

// ============================ gemm0v: V = [L|C]@U (fp16, UNSCALED) ============================
// Independent of the edge/build chain — runs on the side stream.
__global__ void __launch_bounds__(256) k_gemm0v(const float* __restrict__ latent,
                                                const float* __restrict__ cond, int n) {
    __shared__ __align__(16) float sW[96 * 64];
    for (int i = threadIdx.x; i < 96 * 64; i += blockDim.x) sW[i] = g_U[i];
    __syncthreads();
    int node = blockIdx.x * blockDim.x + threadIdx.x;
    if (node >= n) return;

    unsigned long long acc[32];
#pragma unroll
    for (int j = 0; j < 32; j++) acc[j] = 0ull;

    const float* pL = latent + (size_t)node * 64;
    const float* pC = cond   + (size_t)node * 32;
#pragma unroll 2
    for (int k = 0; k < 96; k += 4) {
        float4 av = (k < 64) ? *reinterpret_cast<const float4*>(pL + k)
                             : *reinterpret_cast<const float4*>(pC + (k - 64));
        unsigned long long p0 = pack2(av.x), p1 = pack2(av.y);
        unsigned long long p2 = pack2(av.z), p3 = pack2(av.w);
        const ulonglong2* w0 = reinterpret_cast<const ulonglong2*>(sW + (k + 0) * 64);
        const ulonglong2* w1 = reinterpret_cast<const ulonglong2*>(sW + (k + 1) * 64);
        const ulonglong2* w2 = reinterpret_cast<const ulonglong2*>(sW + (k + 2) * 64);
        const ulonglong2* w3 = reinterpret_cast<const ulonglong2*>(sW + (k + 3) * 64);
#pragma unroll
        for (int j = 0; j < 16; j++) {
            ulonglong2 q;
            q = w0[j]; acc[2*j] = ffma2(p0, q.x, acc[2*j]); acc[2*j+1] = ffma2(p0, q.y, acc[2*j+1]);
            q = w1[j]; acc[2*j] = ffma2(p1, q.x, acc[2*j]); acc[2*j+1] = ffma2(p1, q.y, acc[2*j+1]);
            q = w2[j]; acc[2*j] = ffma2(p2, q.x, acc[2*j]); acc[2*j+1] = ffma2(p2, q.y, acc[2*j+1]);
            q = w3[j]; acc[2*j] = ffma2(p3, q.x, acc[2*j]); acc[2*j+1] = ffma2(p3, q.y, acc[2*j+1]);
        }
    }

    __half* yp = g_T0 + (size_t)node * 64;
#pragma unroll
    for (int j = 0; j < 8; j++) {
        float2 f0 = unpack2(acc[4*j+0]);
        float2 f1 = unpack2(acc[4*j+1]);
        float2 f2 = unpack2(acc[4*j+2]);
        float2 f3 = unpack2(acc[4*j+3]);
        __half2 h0 = __floats2half2_rn(f0.x, f0.y);
        __half2 h1 = __floats2half2_rn(f1.x, f1.y);
        __half2 h2 = __floats2half2_rn(f2.x, f2.y);
        __half2 h3 = __floats2half2_rn(f3.x, f3.y);
        uint4 u = make_uint4(*reinterpret_cast<unsigned*>(&h0), *reinterpret_cast<unsigned*>(&h1),
                             *reinterpret_cast<unsigned*>(&h2), *reinterpret_cast<unsigned*>(&h3));
        *reinterpret_cast<uint4*>(yp + 8 * j) = u;
    }
}

// ============================ join: T0 *= dinv (in place), finalize a1/at ============================
__global__ void k_scale_a1(int n) {
    int idx = blockIdx.x * blockDim.x + threadIdx.x;
    if (idx >= n * 8) return;
    int node = idx >> 3;
    int c = (idx & 7) * 8;
    float dn = g_dinv[node];
    if ((idx & 7) == 0) {
        float a1 = dn * (g_a1f[node] + dn);
        g_a1[node] = a1;
        g_at[node] = dn * a1;
    }
    __half* p = g_T0 + (size_t)node * 64 + c;
    uint4 u = *reinterpret_cast<uint4*>(p);
    __half2* h = reinterpret_cast<__half2*>(&u);
#pragma unroll
    for (int q = 0; q < 4; q++) {
        float2 f = __half22float2(h[q]);
        h[q] = __floats2half2_rn(f.x * dn, f.y * dn);
    }
    *reinterpret_cast<uint4*>(p) = u;
}

// a2 = P·a1 = dinv[c]·( sum at[src] + at[c] )   (side stream, concurrent with agg1)
__global__ void k_a2(int n) {
    int wid  = (blockIdx.x * blockDim.x + threadIdx.x) >> 5;
    int lane = threadIdx.x & 31;
    if (wid >= n) return;
    int beg = g_off[wid], end = g_off[wid + 1];
    float acc = 0.f;
    for (int e = beg + lane; e < end; e += 32) acc += g_at[g_src[e]];
    for (int d = 16; d; d >>= 1) acc += __shfl_down_sync(0xffffffffu, acc, d);
    if (lane == 0) g_a2[wid] = g_dinv[wid] * (acc + g_at[wid]);
}

// ============================ weightless aggregation ============================
template <int MODE>
__global__ void __launch_bounds__(256) k_aggp(const __half* __restrict__ X,
                                              void* __restrict__ Yv, int n) {
    int wid  = (blockIdx.x * blockDim.x + threadIdx.x) >> 5;
    int lane = threadIdx.x & 31;
    if (wid >= n) return;

    const int f0 = lane * 2;
    int e = g_off[wid];
    const int end = g_off[wid + 1];
    float a0 = 0.f, a1v = 0.f;

#define GATH(SRC) { __half2 h = *reinterpret_cast<const __half2*>(X + (size_t)(SRC) * 64 + f0); \
                    float2 f = __half22float2(h); a0 += f.x; a1v += f.y; }

    for (; e + 8 <= end; e += 8) {
        int s0 = g_src[e+0], s1 = g_src[e+1], s2 = g_src[e+2], s3 = g_src[e+3];
        int s4 = g_src[e+4], s5 = g_src[e+5], s6 = g_src[e+6], s7 = g_src[e+7];
        GATH(s0) GATH(s1) GATH(s2) GATH(s3) GATH(s4) GATH(s5) GATH(s6) GATH(s7)
    }
    for (; e < end; ++e) { int s = g_src[e]; GATH(s) }
    GATH(wid)  // self loop
#undef GATH

    float dn = g_dinv[wid];
    if (MODE == 0) {
        float s = dn * dn;
        __half2 h = __floats2half2_rn(a0 * s, a1v * s);
        *reinterpret_cast<__half2*>((__half*)Yv + (size_t)wid * 64 + f0) = h;
    } else {
        *reinterpret_cast<float2*>((float*)Yv + (size_t)wid * 64 + f0) =
            make_float2(a0 * dn, a1v * dn);
    }
}

// ============================ final GEMM ============================
__global__ void __launch_bounds__(256) k_gemm_final(const float* __restrict__ A,
                                                    const float* __restrict__ Wg,
                                                    float* __restrict__ Y, int n) {
    __shared__ __align__(16) float sW[64 * 64];
    __shared__ float sc[64], se[64], sf[64];
    for (int i = threadIdx.x; i < 64 * 64; i += blockDim.x) sW[i] = Wg[i];
    if (threadIdx.x < 64) {
        sc[threadIdx.x] = g_c4[threadIdx.x];
        se[threadIdx.x] = g_e4[threadIdx.x];
        sf[threadIdx.x] = g_f4[threadIdx.x];
    }
    __syncthreads();
    int node = blockIdx.x * blockDim.x + threadIdx.x;
    if (node >= n) return;

    unsigned long long acc[32];
#pragma unroll
    for (int j = 0; j < 32; j++) acc[j] = 0ull;

    const float* arow = A + (size_t)node * 64;
#pragma unroll 2
    for (int k = 0; k < 64; k += 4) {
        float4 av = *reinterpret_cast<const float4*>(arow + k);
        unsigned long long p0 = pack2(av.x), p1 = pack2(av.y);
        unsigned long long p2 = pack2(av.z), p3 = pack2(av.w);
        const ulonglong2* w0 = reinterpret_cast<const ulonglong2*>(sW + (k + 0) * 64);
        const ulonglong2* w1 = reinterpret_cast<const ulonglong2*>(sW + (k + 1) * 64);
        const ulonglong2* w2 = reinterpret_cast<const ulonglong2*>(sW + (k + 2) * 64);
        const ulonglong2* w3 = reinterpret_cast<const ulonglong2*>(sW + (k + 3) * 64);
#pragma unroll
        for (int j = 0; j < 16; j++) {
            ulonglong2 q;
            q = w0[j]; acc[2*j] = ffma2(p0, q.x, acc[2*j]); acc[2*j+1] = ffma2(p0, q.y, acc[2*j+1]);
            q = w1[j]; acc[2*j] = ffma2(p1, q.x, acc[2*j]); acc[2*j+1] = ffma2(p1, q.y, acc[2*j+1]);
            q = w2[j]; acc[2*j] = ffma2(p2, q.x, acc[2*j]); acc[2*j+1] = ffma2(p2, q.y, acc[2*j+1]);
            q = w3[j]; acc[2*j] = ffma2(p3, q.x, acc[2*j]); acc[2*j+1] = ffma2(p3, q.y, acc[2*j+1]);
        }
    }

    float av1 = g_a1[node], av2 = g_a2[node];
    float* yrow = Y + (size_t)node * 64;
#pragma unroll
    for (int j = 0; j < 16; j++) {
        float2 lo = unpack2(acc[2*j]);
        float2 hi = unpack2(acc[2*j+1]);
        int c0 = 4 * j;
        float4 o;
        o.x = lo.x + av2 * sc[c0+0] + av1 * se[c0+0] + sf[c0+0];
        o.y = lo.y + av2 * sc[c0+1] + av1 * se[c0+1] + sf[c0+1];
        o.z = hi.x + av2 * sc[c0+2] + av1 * se[c0+2] + sf[c0+2];
        o.w = hi.y + av2 * sc[c0+3] + av1 * se[c0+3] + sf[c0+3];
        *reinterpret_cast<float4*>(yrow + c0) = o;
    }
}

// ============================ launch ============================

extern "C" void kernel_launch(void* const* d_in, const int* in_sizes, int n_in,
                              void* d_out, int out_size) {
    const float* latent = (const float*)d_in[0];
    const float* cond   = (const float*)d_in[1];
    const int*   edge   = (const int*)  d_in[2];
    const float* W1 = (const float*)d_in[3];
    const float* b1 = (const float*)d_in[4];
    const float* W2 = (const float*)d_in[5];
    const float* b2 = (const float*)d_in[6];
    const float* W3 = (const float*)d_in[7];
    const float* b3 = (const float*)d_in[8];
    const float* W4 = (const float*)d_in[9];
    const float* b4 = (const float*)d_in[10];

    const int n = in_sizes[0] / 64;      // 100000
    const int E = in_sizes[2] / 2;       // 1600000
    const int* row = edge;
    const int* col = edge + E;

    static int* pCnt = nullptr;
    static __half *pT0 = nullptr, *pT1 = nullptr, *pT2 = nullptr;
    static float *pY3 = nullptr;
    static cudaStream_t sB = nullptr;
    static cudaEvent_t ev0 = nullptr, evG0 = nullptr, evScale = nullptr, evA2 = nullptr;
    if (!pCnt) {
        cudaGetSymbolAddress((void**)&pCnt, g_cnt);
        cudaGetSymbolAddress((void**)&pT0,  g_T0);
        cudaGetSymbolAddress((void**)&pT1,  g_T1);
        cudaGetSymbolAddress((void**)&pT2,  g_T2);
        cudaGetSymbolAddress((void**)&pY3,  g_Y3);
        cudaStreamCreateWithFlags(&sB, cudaStreamNonBlocking);
        cudaEventCreateWithFlags(&ev0,     cudaEventDisableTiming);
        cudaEventCreateWithFlags(&evG0,    cudaEventDisableTiming);
        cudaEventCreateWithFlags(&evScale, cudaEventDisableTiming);
        cudaEventCreateWithFlags(&evA2,    cudaEventDisableTiming);
    }

    const int TB  = 256;
    const int gN  = (n + TB - 1) / TB;
    const int gE  = (E + TB - 1) / TB;
    const int nbS = (n + 1023) / 1024;
    const int gN1 = (n + 1 + TB - 1) / TB;
    const int gW  = (n + 7) / 8;           // warp per node, 8 warps/block
    const int gS  = (n * 8 + TB - 1) / TB; // scale kernel

    // ---- fork: side stream B handles the weight path ----
    cudaEventRecord(ev0, 0);
    cudaStreamWaitEvent(sB, ev0, 0);
    k_wprep2<<<25, 256, 0, sB>>>(W1, W2, W3, W4, b1, b2, b3, b4);
    k_gemm0v<<<gN, TB, 0, sB>>>(latent, cond, n);   // V = [L|C]@U (unscaled)
    cudaEventRecord(evG0, sB);

    // ---- main stream: edge/build chain ----
    cudaMemsetAsync(pCnt, 0, (size_t)n * sizeof(int));
    k_hist<<<gE, TB>>>(col, E);
    k_scan_local<<<nbS, 1024>>>(n);
    k_scan_bsum<<<1, 1024>>>(nbS);
    k_scan_add<<<gN1, TB>>>(n, E);
    k_fill<<<gE, TB>>>(row, col, E);

    // ---- join: scale T0 by dinv in place, finalize a1/at ----
    cudaStreamWaitEvent(0, evG0, 0);
    k_scale_a1<<<gS, TB>>>(n);
    cudaEventRecord(evScale, 0);

    // ---- side stream: a2 (concurrent with agg passes) ----
    cudaStreamWaitEvent(sB, evScale, 0);
    k_a2<<<gW, TB, 0, sB>>>(n);
    cudaEventRecord(evA2, sB);

    // ---- three weightless aggregation passes ----
    k_aggp<0><<<gW, TB>>>(pT0, pT1, n);
    k_aggp<0><<<gW, TB>>>(pT1, pT2, n);
    k_aggp<1><<<gW, TB>>>(pT2, pY3, n);

    // ---- out = Y3@W4 + a2·c4 + a1·e4 + f4 ----
    cudaStreamWaitEvent(0, evA2, 0);
    k_gemm_final<<<gN, TB>>>(pY3, W4, (float*)d_out, n);
}